// round 2
// baseline (speedup 1.0000x reference)
#include <cuda_runtime.h>
#include <cuda_bf16.h>
#include <math.h>

// Problem constants (shapes from setup_inputs)
#define NMAX 100000
#define D    128

// Scratch (device globals — no allocation allowed in kernel_launch)
__device__ float g_bufA[(size_t)NMAX * D];
__device__ float g_bufB[(size_t)NMAX * D];
__device__ float g_bufC[(size_t)NMAX * D];
__device__ float g_deg[NMAX];
__device__ float g_dinv[NMAX];
__device__ int   g_idx64;   // 1 if edge_index is int64, 0 if int32

// ---------------------------------------------------------------------------
// Detect edge_index dtype: int64 values are all < NMAX; int32 data read as
// int64 combines two random indices -> huge values. One thread, 16 samples.
// ---------------------------------------------------------------------------
__global__ void k_detect(const void* __restrict__ ei) {
    const long long* p = (const long long*)ei;
    int ok = 1;
    for (int i = 0; i < 16; i++) {
        long long v = p[i];
        if (v < 0 || v >= NMAX) ok = 0;
    }
    g_idx64 = ok;
}

__device__ __forceinline__ int edge_at(const void* ei, long long idx) {
    if (g_idx64) return (int)((const long long*)ei)[idx];
    return ((const int*)ei)[idx];
}

// ---------------------------------------------------------------------------
// Degree / dinv
// ---------------------------------------------------------------------------
__global__ void k_init_deg(float* deg, int n) {
    int i = blockIdx.x * blockDim.x + threadIdx.x;
    if (i < n) deg[i] = 1.0f;  // self-loop
}

__global__ void k_count_deg(const void* __restrict__ ei, float* deg, int e) {
    int i = blockIdx.x * blockDim.x + threadIdx.x;
    if (i < e) {
        int d = edge_at(ei, (long long)e + i);  // dst row
        atomicAdd(&deg[d], 1.0f);
    }
}

__global__ void k_dinv(const float* __restrict__ deg, float* dinv, int n) {
    int i = blockIdx.x * blockDim.x + threadIdx.x;
    if (i < n) dinv[i] = rsqrtf(deg[i]);
}

// ---------------------------------------------------------------------------
// GEMM: C[N,128] = act(A[N,K] @ W[K,128] (+ bias))
// Tile 64 rows x 128 cols, 256 threads, 8x4 microtile per thread, BK=16.
// act: 0 = none (bias may be null), 1 = leaky relu (slope 0.01)
// ---------------------------------------------------------------------------
__global__ __launch_bounds__(256) void k_gemm(
    const float* __restrict__ A, const float* __restrict__ W,
    const float* __restrict__ bias, float* __restrict__ C,
    int N, int K, int act)
{
    __shared__ float As[64][16];
    __shared__ float Ws[16][128];

    const int cg = threadIdx.x & 31;   // col group: cols cg*4 .. cg*4+3
    const int rg = threadIdx.x >> 5;   // row group: rows rg*8 .. rg*8+7
    const int rowBase = blockIdx.x * 64;

    float acc[8][4];
#pragma unroll
    for (int r = 0; r < 8; r++)
#pragma unroll
        for (int c = 0; c < 4; c++) acc[r][c] = 0.0f;

    for (int k0 = 0; k0 < K; k0 += 16) {
        // Load A tile: 64x16 = 1024 elems, 4 per thread
#pragma unroll
        for (int i = 0; i < 4; i++) {
            int e = threadIdx.x + i * 256;
            int r = e >> 4, kk = e & 15;
            int grow = rowBase + r, gk = k0 + kk;
            float v = 0.0f;
            if (grow < N && gk < K) v = A[(size_t)grow * K + gk];
            As[r][kk] = v;
        }
        // Load W tile: 16x128 = 2048 elems, 8 per thread
#pragma unroll
        for (int i = 0; i < 8; i++) {
            int e = threadIdx.x + i * 256;
            int kk = e >> 7, c = e & 127;
            int gk = k0 + kk;
            Ws[kk][c] = (gk < K) ? W[(size_t)gk * D + c] : 0.0f;
        }
        __syncthreads();

#pragma unroll
        for (int kk = 0; kk < 16; kk++) {
            float4 wv = *reinterpret_cast<const float4*>(&Ws[kk][cg * 4]);
            float av[8];
#pragma unroll
            for (int r = 0; r < 8; r++) av[r] = As[rg * 8 + r][kk];  // warp-broadcast
#pragma unroll
            for (int r = 0; r < 8; r++) {
                acc[r][0] += av[r] * wv.x;
                acc[r][1] += av[r] * wv.y;
                acc[r][2] += av[r] * wv.z;
                acc[r][3] += av[r] * wv.w;
            }
        }
        __syncthreads();
    }

    float b0 = 0, b1 = 0, b2 = 0, b3 = 0;
    if (bias) {
        b0 = bias[cg * 4 + 0]; b1 = bias[cg * 4 + 1];
        b2 = bias[cg * 4 + 2]; b3 = bias[cg * 4 + 3];
    }
#pragma unroll
    for (int r = 0; r < 8; r++) {
        int grow = rowBase + rg * 8 + r;
        if (grow >= N) continue;
        float4 o;
        o.x = acc[r][0] + b0; o.y = acc[r][1] + b1;
        o.z = acc[r][2] + b2; o.w = acc[r][3] + b3;
        if (act == 1) {
            o.x = o.x >= 0.f ? o.x : 0.01f * o.x;
            o.y = o.y >= 0.f ? o.y : 0.01f * o.y;
            o.z = o.z >= 0.f ? o.z : 0.01f * o.z;
            o.w = o.w >= 0.f ? o.w : 0.01f * o.w;
        }
        *reinterpret_cast<float4*>(&C[(size_t)grow * D + cg * 4]) = o;
    }
}

// ---------------------------------------------------------------------------
// agg init: agg[n][j] = t[n][j] * dinv[n]^2 + b[j]   (self loop + bias)
// ---------------------------------------------------------------------------
__global__ void k_init_agg(const float* __restrict__ t, const float* __restrict__ dinv,
                           const float* __restrict__ bias, float* __restrict__ agg, int n)
{
    int idx = blockIdx.x * blockDim.x + threadIdx.x;
    if (idx >= n * D) return;
    int node = idx >> 7, j = idx & 127;
    float di = dinv[node];
    agg[idx] = t[idx] * di * di + bias[j];
}

// ---------------------------------------------------------------------------
// Edge scatter: agg[dst] += t[src] * dinv[src]*dinv[dst].  One warp per edge;
// each lane does 4 coalesced loads + 4 coalesced atomicAdds.
// ---------------------------------------------------------------------------
__global__ __launch_bounds__(256) void k_scatter(
    const float* __restrict__ t, const void* __restrict__ ei,
    const float* __restrict__ dinv, float* __restrict__ agg, int E)
{
    int warp = (blockIdx.x * blockDim.x + threadIdx.x) >> 5;
    int lane = threadIdx.x & 31;
    if (warp >= E) return;
    int s = edge_at(ei, warp);
    int d = edge_at(ei, (long long)E + warp);
    float norm = dinv[s] * dinv[d];
    const float* trow = t + (size_t)s * D;
    float* arow = agg + (size_t)d * D;
#pragma unroll
    for (int j = 0; j < 4; j++) {
        int c = lane + j * 32;
        atomicAdd(&arow[c], trow[c] * norm);
    }
}

// ---------------------------------------------------------------------------
// Final projection: out[n][0..1] = h3[n] @ W_o2 + b_o2.  One warp per row.
// ---------------------------------------------------------------------------
__global__ __launch_bounds__(256) void k_final(
    const float* __restrict__ h3, const float* __restrict__ W2,
    const float* __restrict__ b2, float* __restrict__ out, int N)
{
    int warp = (blockIdx.x * blockDim.x + threadIdx.x) >> 5;
    int lane = threadIdx.x & 31;
    if (warp >= N) return;
    float4 h = *reinterpret_cast<const float4*>(&h3[(size_t)warp * D + lane * 4]);
    float s0 = 0.f, s1 = 0.f;
    const float* hv = reinterpret_cast<const float*>(&h);
#pragma unroll
    for (int j = 0; j < 4; j++) {
        int k = lane * 4 + j;
        s0 += hv[j] * W2[k * 2 + 0];
        s1 += hv[j] * W2[k * 2 + 1];
    }
#pragma unroll
    for (int off = 16; off; off >>= 1) {
        s0 += __shfl_xor_sync(0xFFFFFFFFu, s0, off);
        s1 += __shfl_xor_sync(0xFFFFFFFFu, s1, off);
    }
    if (lane == 0) {
        out[(size_t)warp * 2 + 0] = s0 + b2[0];
        out[(size_t)warp * 2 + 1] = s1 + b2[1];
    }
}

// ---------------------------------------------------------------------------
// Host launcher
// ---------------------------------------------------------------------------
extern "C" void kernel_launch(void* const* d_in, const int* in_sizes, int n_in,
                              void* d_out, int out_size)
{
    const float* x    = (const float*)d_in[0];
    const void*  ei   = d_in[1];           // int32 or int64, detected on device
    // d_in[2] = edge_type (unused)
    const float* W_in = (const float*)d_in[3];
    const float* b_in = (const float*)d_in[4];
    const float* W_g  = (const float*)d_in[5];
    const float* b_g  = (const float*)d_in[6];
    const float* W_o1 = (const float*)d_in[7];
    const float* b_o1 = (const float*)d_in[8];
    const float* W_o2 = (const float*)d_in[9];
    const float* b_o2 = (const float*)d_in[10];
    float*       out  = (float*)d_out;

    const int ND = 239;
    const int N  = in_sizes[0] / ND;
    const int E  = in_sizes[1] / 2;

    float *bufA, *bufB, *bufC, *deg, *dinv;
    cudaGetSymbolAddress((void**)&bufA, g_bufA);
    cudaGetSymbolAddress((void**)&bufB, g_bufB);
    cudaGetSymbolAddress((void**)&bufC, g_bufC);
    cudaGetSymbolAddress((void**)&deg,  g_deg);
    cudaGetSymbolAddress((void**)&dinv, g_dinv);

    const int TB = 256;
    // 0: detect index dtype
    k_detect<<<1, 1>>>(ei);
    // 1-3: degree + dinv
    k_init_deg<<<(N + TB - 1) / TB, TB>>>(deg, N);
    k_count_deg<<<(E + TB - 1) / TB, TB>>>(ei, deg, E);
    k_dinv<<<(N + TB - 1) / TB, TB>>>(deg, dinv, N);

    const int gemmGrid = (N + 63) / 64;
    // 4: h0 = leaky(x @ W_in + b_in)           -> bufA
    k_gemm<<<gemmGrid, TB>>>(x, W_in, b_in, bufA, N, ND, 1);

    // conv 1: t = h0 @ W_g -> bufB; h1 = scatter(t) + self + b_g -> bufC
    k_gemm<<<gemmGrid, TB>>>(bufA, W_g, nullptr, bufB, N, D, 0);
    k_init_agg<<<((size_t)N * D + TB - 1) / TB, TB>>>(bufB, dinv, b_g, bufC, N);
    k_scatter<<<((size_t)E * 32 + TB - 1) / TB, TB>>>(bufB, ei, dinv, bufC, E);

    // conv 2: t = h1 @ W_g -> bufA; h2 -> bufB
    k_gemm<<<gemmGrid, TB>>>(bufC, W_g, nullptr, bufA, N, D, 0);
    k_init_agg<<<((size_t)N * D + TB - 1) / TB, TB>>>(bufA, dinv, b_g, bufB, N);
    k_scatter<<<((size_t)E * 32 + TB - 1) / TB, TB>>>(bufA, ei, dinv, bufB, E);

    // h3 = leaky(h2 @ W_o1 + b_o1)             -> bufC
    k_gemm<<<gemmGrid, TB>>>(bufB, W_o1, b_o1, bufC, N, D, 1);

    // out = h3 @ W_o2 + b_o2
    k_final<<<((size_t)N * 32 + TB - 1) / TB, TB>>>(bufC, W_o2, b_o2, out, N);
}

// round 7
// speedup vs baseline: 1.2339x; 1.2339x over previous
#include <cuda_runtime.h>
#include <cuda_bf16.h>
#include <cstdint>
#include <math.h>

#define NMAX 100000
#define D    128

// Scratch
__device__ float g_bufA[(size_t)NMAX * D];
__device__ float g_bufB[(size_t)NMAX * D];
__device__ float g_bufC[(size_t)NMAX * D];
__device__ float g_deg[NMAX];
__device__ float g_dinv[NMAX];
__device__ int   g_idx64;

__device__ __forceinline__ float leaky(float v) { return v >= 0.f ? v : 0.01f * v; }

// ---------------------------------------------------------------------------
// m16n8k16 bf16 MMA (portable HMMA path, works on plain sm_103 target)
// ---------------------------------------------------------------------------
__device__ __forceinline__ void mma16816(float* c, const uint32_t* a, const uint32_t* b) {
    asm volatile(
        "mma.sync.aligned.m16n8k16.row.col.f32.bf16.bf16.f32 "
        "{%0,%1,%2,%3}, {%4,%5,%6,%7}, {%8,%9}, {%0,%1,%2,%3};"
        : "+f"(c[0]), "+f"(c[1]), "+f"(c[2]), "+f"(c[3])
        : "r"(a[0]), "r"(a[1]), "r"(a[2]), "r"(a[3]), "r"(b[0]), "r"(b[1]));
}

__device__ __forceinline__ uint32_t pack_hi(float a0, float a1) {
    __nv_bfloat16 h0 = __float2bfloat16(a0), h1 = __float2bfloat16(a1);
    return (uint32_t)__bfloat16_as_ushort(h0) | ((uint32_t)__bfloat16_as_ushort(h1) << 16);
}
__device__ __forceinline__ uint32_t pack_lo(float a0, float a1) {
    __nv_bfloat16 h0 = __float2bfloat16(a0), h1 = __float2bfloat16(a1);
    __nv_bfloat16 l0 = __float2bfloat16(a0 - __bfloat162float(h0));
    __nv_bfloat16 l1 = __float2bfloat16(a1 - __bfloat162float(h1));
    return (uint32_t)__bfloat16_as_ushort(l0) | ((uint32_t)__bfloat16_as_ushort(l1) << 16);
}

// ---------------------------------------------------------------------------
// GEMM: C = A[M,K] @ W[K,128].  Block tile 128x128, 8 warps (2x4), 64x32/warp.
// K staged in chunks of 32 through smem; bf16 hi/lo 3-pass for fp32 accuracy.
// smem row stride = 40 halves (80B) -> conflict-free frag loads.
// mode 1: C0 = leaky(acc + bias)
// mode 2: C0 = acc;  C1 = acc * dinv[row]^2 + bias   (GCN self-loop init)
// ---------------------------------------------------------------------------
#define RS 40  // smem row stride in halves

__global__ __launch_bounds__(256, 2) void k_gemm_mma(
    const float* __restrict__ A, const float* __restrict__ W,
    const float* __restrict__ bias, const float* __restrict__ dinv,
    float* __restrict__ C0, float* __restrict__ C1,
    int M, int K, int lda, int mode)
{
    __shared__ float sBias[128];
    __shared__ __align__(16) __nv_bfloat16 AsHi[128 * RS];
    __shared__ __align__(16) __nv_bfloat16 AsLo[128 * RS];
    __shared__ __align__(16) __nv_bfloat16 BsHi[128 * RS];  // Bs[n][k] = W[k][n]
    __shared__ __align__(16) __nv_bfloat16 BsLo[128 * RS];

    const int tid  = threadIdx.x;
    const int wid  = tid >> 5;
    const int lane = tid & 31;
    const int g    = lane >> 2;   // group id (row within frag)
    const int tig  = lane & 3;    // thread in group
    const int wm   = (wid >> 2) * 64;   // warp row offset (0/64)
    const int wn   = (wid & 3) * 32;    // warp col offset (0/32/64/96)
    const int rowBase = blockIdx.x * 128;

    if (tid < 128) sBias[tid] = bias[tid];

    float acc[4][4][4];
#pragma unroll
    for (int mt = 0; mt < 4; mt++)
#pragma unroll
        for (int nt = 0; nt < 4; nt++)
#pragma unroll
            for (int j = 0; j < 4; j++) acc[mt][nt][j] = 0.f;

    const int nStages = (K + 31) >> 5;
    for (int st = 0; st < nStages; st++) {
        const int k0 = st << 5;

        // ---- stage A tile: 128 rows x 32 cols (as 16 b32-words per row) ----
#pragma unroll
        for (int i = 0; i < 8; i++) {
            int w = tid + i * 256;       // 0..2047
            int row = w >> 4, kw = w & 15;
            int grow = rowBase + row, gk = k0 + kw * 2;
            float a0 = 0.f, a1 = 0.f;
            if (grow < M) {
                const float* ap = A + (size_t)grow * lda;
                if (gk < K)     a0 = ap[gk];
                if (gk + 1 < K) a1 = ap[gk + 1];
            }
            int so = row * RS + kw * 2;
            *(uint32_t*)(AsHi + so) = pack_hi(a0, a1);
            *(uint32_t*)(AsLo + so) = pack_lo(a0, a1);
        }
        // ---- stage B tile: Bs[n][k] from W[k][n] (coalesced over n) ----
#pragma unroll
        for (int i = 0; i < 8; i++) {
            int w = tid + i * 256;
            int n = w & 127, kw = w >> 7;  // kw 0..15
            int gk = k0 + kw * 2;
            float b0 = (gk < K)     ? W[(size_t)gk * D + n]       : 0.f;
            float b1 = (gk + 1 < K) ? W[(size_t)(gk + 1) * D + n] : 0.f;
            int so = n * RS + kw * 2;
            *(uint32_t*)(BsHi + so) = pack_hi(b0, b1);
            *(uint32_t*)(BsLo + so) = pack_lo(b0, b1);
        }
        __syncthreads();

        // ---- compute: two k16 sub-steps ----
#pragma unroll
        for (int kk = 0; kk < 32; kk += 16) {
            uint32_t bh[4][2], bl[4][2];
#pragma unroll
            for (int nt = 0; nt < 4; nt++) {
                int n = wn + nt * 8 + g;
                int kb = kk + 2 * tig;
                bh[nt][0] = *(uint32_t*)(BsHi + n * RS + kb);
                bh[nt][1] = *(uint32_t*)(BsHi + n * RS + kb + 8);
                bl[nt][0] = *(uint32_t*)(BsLo + n * RS + kb);
                bl[nt][1] = *(uint32_t*)(BsLo + n * RS + kb + 8);
            }
#pragma unroll
            for (int mt = 0; mt < 4; mt++) {
                int r = wm + mt * 16 + g;
                int ka = kk + 2 * tig;
                uint32_t ah[4], al[4];
                ah[0] = *(uint32_t*)(AsHi + r * RS + ka);
                ah[1] = *(uint32_t*)(AsHi + (r + 8) * RS + ka);
                ah[2] = *(uint32_t*)(AsHi + r * RS + ka + 8);
                ah[3] = *(uint32_t*)(AsHi + (r + 8) * RS + ka + 8);
                al[0] = *(uint32_t*)(AsLo + r * RS + ka);
                al[1] = *(uint32_t*)(AsLo + (r + 8) * RS + ka);
                al[2] = *(uint32_t*)(AsLo + r * RS + ka + 8);
                al[3] = *(uint32_t*)(AsLo + (r + 8) * RS + ka + 8);
#pragma unroll
                for (int nt = 0; nt < 4; nt++) {
                    mma16816(acc[mt][nt], ah, bh[nt]);
                    mma16816(acc[mt][nt], ah, bl[nt]);
                    mma16816(acc[mt][nt], al, bh[nt]);
                }
            }
        }
        __syncthreads();
    }

    // ---- epilogue ----
#pragma unroll
    for (int mt = 0; mt < 4; mt++) {
        int r0 = rowBase + wm + mt * 16 + g;
        int r1 = r0 + 8;
        bool v0 = r0 < M, v1 = r1 < M;
        float dv0 = 0.f, dv1 = 0.f;
        if (mode == 2) {
            if (v0) { float t = dinv[r0]; dv0 = t * t; }
            if (v1) { float t = dinv[r1]; dv1 = t * t; }
        }
#pragma unroll
        for (int nt = 0; nt < 4; nt++) {
            int cn = wn + nt * 8 + 2 * tig;
            float b0 = sBias[cn], b1 = sBias[cn + 1];
            float* c = acc[mt][nt];
            if (mode == 1) {
                if (v0) {
                    float2 o = { leaky(c[0] + b0), leaky(c[1] + b1) };
                    *(float2*)(C0 + (size_t)r0 * D + cn) = o;
                }
                if (v1) {
                    float2 o = { leaky(c[2] + b0), leaky(c[3] + b1) };
                    *(float2*)(C0 + (size_t)r1 * D + cn) = o;
                }
            } else {  // mode 2
                if (v0) {
                    float2 t = { c[0], c[1] };
                    float2 a = { c[0] * dv0 + b0, c[1] * dv0 + b1 };
                    *(float2*)(C0 + (size_t)r0 * D + cn) = t;
                    *(float2*)(C1 + (size_t)r0 * D + cn) = a;
                }
                if (v1) {
                    float2 t = { c[2], c[3] };
                    float2 a = { c[2] * dv1 + b0, c[3] * dv1 + b1 };
                    *(float2*)(C0 + (size_t)r1 * D + cn) = t;
                    *(float2*)(C1 + (size_t)r1 * D + cn) = a;
                }
            }
        }
    }
}

// ---------------------------------------------------------------------------
// Edge index dtype detection + degree helpers
// ---------------------------------------------------------------------------
__global__ void k_detect(const void* __restrict__ ei) {
    const long long* p = (const long long*)ei;
    int ok = 1;
    for (int i = 0; i < 16; i++) {
        long long v = p[i];
        if (v < 0 || v >= NMAX) ok = 0;
    }
    g_idx64 = ok;
}
__device__ __forceinline__ int edge_at(const void* ei, long long idx) {
    if (g_idx64) return (int)((const long long*)ei)[idx];
    return ((const int*)ei)[idx];
}

__global__ void k_init_deg(float* deg, int n) {
    int i = blockIdx.x * blockDim.x + threadIdx.x;
    if (i < n) deg[i] = 1.0f;
}
__global__ void k_count_deg(const void* __restrict__ ei, float* deg, int e) {
    int i = blockIdx.x * blockDim.x + threadIdx.x;
    if (i < e) atomicAdd(&deg[edge_at(ei, (long long)e + i)], 1.0f);
}
__global__ void k_dinv(const float* __restrict__ deg, float* dinv, int n) {
    int i = blockIdx.x * blockDim.x + threadIdx.x;
    if (i < n) dinv[i] = rsqrtf(deg[i]);
}

// ---------------------------------------------------------------------------
// Edge scatter: one warp per edge, one red.global.add.v4.f32 per lane.
// ---------------------------------------------------------------------------
__global__ __launch_bounds__(256) void k_scatter(
    const float* __restrict__ t, const void* __restrict__ ei,
    const float* __restrict__ dinv, float* __restrict__ agg, int E)
{
    int warp = (blockIdx.x * blockDim.x + threadIdx.x) >> 5;
    int lane = threadIdx.x & 31;
    if (warp >= E) return;
    int s = edge_at(ei, warp);
    int d = edge_at(ei, (long long)E + warp);
    float norm = dinv[s] * dinv[d];
    float4 v = *(const float4*)(t + (size_t)s * D + lane * 4);
    v.x *= norm; v.y *= norm; v.z *= norm; v.w *= norm;
    float* p = agg + (size_t)d * D + lane * 4;
    asm volatile("red.global.add.v4.f32 [%0], {%1, %2, %3, %4};"
                 :: "l"(p), "f"(v.x), "f"(v.y), "f"(v.z), "f"(v.w) : "memory");
}

// ---------------------------------------------------------------------------
// Final projection: out[n][0..1] = h3[n] @ W_o2 + b_o2.  One warp per row.
// ---------------------------------------------------------------------------
__global__ __launch_bounds__(256) void k_final(
    const float* __restrict__ h3, const float* __restrict__ W2,
    const float* __restrict__ b2, float* __restrict__ out, int N)
{
    int warp = (blockIdx.x * blockDim.x + threadIdx.x) >> 5;
    int lane = threadIdx.x & 31;
    if (warp >= N) return;
    float4 h = *reinterpret_cast<const float4*>(&h3[(size_t)warp * D + lane * 4]);
    float s0 = 0.f, s1 = 0.f;
    const float* hv = reinterpret_cast<const float*>(&h);
#pragma unroll
    for (int j = 0; j < 4; j++) {
        int k = lane * 4 + j;
        s0 += hv[j] * W2[k * 2 + 0];
        s1 += hv[j] * W2[k * 2 + 1];
    }
#pragma unroll
    for (int off = 16; off; off >>= 1) {
        s0 += __shfl_xor_sync(0xFFFFFFFFu, s0, off);
        s1 += __shfl_xor_sync(0xFFFFFFFFu, s1, off);
    }
    if (lane == 0) {
        out[(size_t)warp * 2 + 0] = s0 + b2[0];
        out[(size_t)warp * 2 + 1] = s1 + b2[1];
    }
}

// ---------------------------------------------------------------------------
// Host launcher
// ---------------------------------------------------------------------------
extern "C" void kernel_launch(void* const* d_in, const int* in_sizes, int n_in,
                              void* d_out, int out_size)
{
    const float* x    = (const float*)d_in[0];
    const void*  ei   = d_in[1];
    const float* W_in = (const float*)d_in[3];
    const float* b_in = (const float*)d_in[4];
    const float* W_g  = (const float*)d_in[5];
    const float* b_g  = (const float*)d_in[6];
    const float* W_o1 = (const float*)d_in[7];
    const float* b_o1 = (const float*)d_in[8];
    const float* W_o2 = (const float*)d_in[9];
    const float* b_o2 = (const float*)d_in[10];
    float*       out  = (float*)d_out;

    const int ND = 239;
    const int N  = in_sizes[0] / ND;
    const int E  = in_sizes[1] / 2;

    float *bufA, *bufB, *bufC, *deg, *dinv;
    cudaGetSymbolAddress((void**)&bufA, g_bufA);
    cudaGetSymbolAddress((void**)&bufB, g_bufB);
    cudaGetSymbolAddress((void**)&bufC, g_bufC);
    cudaGetSymbolAddress((void**)&deg,  g_deg);
    cudaGetSymbolAddress((void**)&dinv, g_dinv);

    const int TB = 256;
    k_detect<<<1, 1>>>(ei);
    k_init_deg<<<(N + TB - 1) / TB, TB>>>(deg, N);
    k_count_deg<<<(E + TB - 1) / TB, TB>>>(ei, deg, E);
    k_dinv<<<(N + TB - 1) / TB, TB>>>(deg, dinv, N);

    const int grid = (N + 127) / 128;
    // G1: h0 = leaky(x @ W_in + b_in) -> A
    k_gemm_mma<<<grid, TB>>>(x, W_in, b_in, nullptr, bufA, nullptr, N, ND, ND, 1);
    // G2: t = h0 @ W_g -> B ; agg = t*dinv^2 + b_g -> C
    k_gemm_mma<<<grid, TB>>>(bufA, W_g, b_g, dinv, bufB, bufC, N, D, D, 2);
    k_scatter<<<((size_t)E * 32 + TB - 1) / TB, TB>>>(bufB, ei, dinv, bufC, E);
    // G3: t = h1 @ W_g -> A ; agg -> B
    k_gemm_mma<<<grid, TB>>>(bufC, W_g, b_g, dinv, bufA, bufB, N, D, D, 2);
    k_scatter<<<((size_t)E * 32 + TB - 1) / TB, TB>>>(bufA, ei, dinv, bufB, E);
    // G4: h3 = leaky(h2 @ W_o1 + b_o1) -> C
    k_gemm_mma<<<grid, TB>>>(bufB, W_o1, b_o1, nullptr, bufC, nullptr, N, D, D, 1);
    // out = h3 @ W_o2 + b_o2
    k_final<<<((size_t)N * 32 + TB - 1) / TB, TB>>>(bufC, W_o2, b_o2, out, N);
}

// round 8
// speedup vs baseline: 1.3364x; 1.0831x over previous
#include <cuda_runtime.h>
#include <cuda_bf16.h>
#include <cstdint>
#include <math.h>

#define NMAX 100000
#define EMAX 640000
#define D    128

// Scratch
__device__ float g_bufA[(size_t)NMAX * D];
__device__ float g_bufB[(size_t)NMAX * D];
__device__ float g_bufC[(size_t)NMAX * D];
__device__ float g_deg[NMAX];
__device__ float g_dinv[NMAX];
__device__ int   g_src32[EMAX];
__device__ int   g_dst32[EMAX];
__device__ float g_norm[EMAX];
__device__ int   g_idx64;

__device__ __forceinline__ float leaky(float v) { return v >= 0.f ? v : 0.01f * v; }

// ---------------------------------------------------------------------------
// m16n8k16 bf16 MMA (portable HMMA path, works on plain sm_103 target)
// ---------------------------------------------------------------------------
__device__ __forceinline__ void mma16816(float* c, const uint32_t* a, const uint32_t* b) {
    asm volatile(
        "mma.sync.aligned.m16n8k16.row.col.f32.bf16.bf16.f32 "
        "{%0,%1,%2,%3}, {%4,%5,%6,%7}, {%8,%9}, {%0,%1,%2,%3};"
        : "+f"(c[0]), "+f"(c[1]), "+f"(c[2]), "+f"(c[3])
        : "r"(a[0]), "r"(a[1]), "r"(a[2]), "r"(a[3]), "r"(b[0]), "r"(b[1]));
}

__device__ __forceinline__ uint32_t pack_hi(float a0, float a1) {
    __nv_bfloat16 h0 = __float2bfloat16(a0), h1 = __float2bfloat16(a1);
    return (uint32_t)__bfloat16_as_ushort(h0) | ((uint32_t)__bfloat16_as_ushort(h1) << 16);
}
__device__ __forceinline__ uint32_t pack_lo(float a0, float a1) {
    __nv_bfloat16 h0 = __float2bfloat16(a0), h1 = __float2bfloat16(a1);
    __nv_bfloat16 l0 = __float2bfloat16(a0 - __bfloat162float(h0));
    __nv_bfloat16 l1 = __float2bfloat16(a1 - __bfloat162float(h1));
    return (uint32_t)__bfloat16_as_ushort(l0) | ((uint32_t)__bfloat16_as_ushort(l1) << 16);
}

// ---------------------------------------------------------------------------
// GEMM: C = A[M,K] @ W[K,128].  Block tile 128x128, 8 warps (2x4), 64x32/warp.
// K staged in 32-chunks; bf16 hi/lo 3-pass.  Register-prefetch pipelining:
// next stage loaded + packed during current stage's mma.
// mode 1: C0 = leaky(acc + bias)
// mode 2: C0 = acc;  C1 = acc * dinv[row]^2 + bias
// ---------------------------------------------------------------------------
#define RS 40  // smem row stride in halves

struct Frag { uint32_t aHi[8], aLo[8], bHi[8], bLo[8]; };

__device__ __forceinline__ void prefetch(
    Frag& f, const float* __restrict__ A, const float* __restrict__ W,
    int rowBase, int M, int K, int lda, int k0, int tid)
{
#pragma unroll
    for (int i = 0; i < 8; i++) {
        int w = tid + i * 256;
        int row = w >> 4, kw = w & 15;
        int grow = rowBase + row, gk = k0 + kw * 2;
        float a0 = 0.f, a1 = 0.f;
        if (grow < M) {
            const float* ap = A + (size_t)grow * lda;
            if (gk < K)     a0 = ap[gk];
            if (gk + 1 < K) a1 = ap[gk + 1];
        }
        f.aHi[i] = pack_hi(a0, a1);
        f.aLo[i] = pack_lo(a0, a1);
    }
#pragma unroll
    for (int i = 0; i < 8; i++) {
        int w = tid + i * 256;
        int n = w & 127, kw = w >> 7;
        int gk = k0 + kw * 2;
        float b0 = (gk < K)     ? W[(size_t)gk * D + n]       : 0.f;
        float b1 = (gk + 1 < K) ? W[(size_t)(gk + 1) * D + n] : 0.f;
        f.bHi[i] = pack_hi(b0, b1);
        f.bLo[i] = pack_lo(b0, b1);
    }
}

__global__ __launch_bounds__(256, 2) void k_gemm_mma(
    const float* __restrict__ A, const float* __restrict__ W,
    const float* __restrict__ bias, const float* __restrict__ dinv,
    float* __restrict__ C0, float* __restrict__ C1,
    int M, int K, int lda, int mode)
{
    __shared__ float sBias[128];
    __shared__ __align__(16) __nv_bfloat16 AsHi[128 * RS];
    __shared__ __align__(16) __nv_bfloat16 AsLo[128 * RS];
    __shared__ __align__(16) __nv_bfloat16 BsHi[128 * RS];  // Bs[n][k] = W[k][n]
    __shared__ __align__(16) __nv_bfloat16 BsLo[128 * RS];

    const int tid  = threadIdx.x;
    const int wid  = tid >> 5;
    const int lane = tid & 31;
    const int g    = lane >> 2;
    const int tig  = lane & 3;
    const int wm   = (wid >> 2) * 64;
    const int wn   = (wid & 3) * 32;
    const int rowBase = blockIdx.x * 128;

    if (tid < 128) sBias[tid] = bias[tid];

    float acc[4][4][4];
#pragma unroll
    for (int mt = 0; mt < 4; mt++)
#pragma unroll
        for (int nt = 0; nt < 4; nt++)
#pragma unroll
            for (int j = 0; j < 4; j++) acc[mt][nt][j] = 0.f;

    const int nStages = (K + 31) >> 5;
    Frag f;
    prefetch(f, A, W, rowBase, M, K, lda, 0, tid);

    for (int st = 0; st < nStages; st++) {
        // ---- commit prefetched regs to smem (short critical section) ----
#pragma unroll
        for (int i = 0; i < 8; i++) {
            int w = tid + i * 256;
            int row = w >> 4, kw = w & 15;
            int so = row * RS + kw * 2;
            *(uint32_t*)(AsHi + so) = f.aHi[i];
            *(uint32_t*)(AsLo + so) = f.aLo[i];
            int n = w & 127, kb = (w >> 7) * 2;
            int sb = n * RS + kb;
            *(uint32_t*)(BsHi + sb) = f.bHi[i];
            *(uint32_t*)(BsLo + sb) = f.bLo[i];
        }
        __syncthreads();

        // ---- issue next-stage loads (overlap with mma below) ----
        if (st + 1 < nStages)
            prefetch(f, A, W, rowBase, M, K, lda, (st + 1) << 5, tid);

        // ---- compute: two k16 sub-steps ----
#pragma unroll
        for (int kk = 0; kk < 32; kk += 16) {
            uint32_t bh[4][2], bl[4][2];
#pragma unroll
            for (int nt = 0; nt < 4; nt++) {
                int n = wn + nt * 8 + g;
                int kb = kk + 2 * tig;
                bh[nt][0] = *(uint32_t*)(BsHi + n * RS + kb);
                bh[nt][1] = *(uint32_t*)(BsHi + n * RS + kb + 8);
                bl[nt][0] = *(uint32_t*)(BsLo + n * RS + kb);
                bl[nt][1] = *(uint32_t*)(BsLo + n * RS + kb + 8);
            }
#pragma unroll
            for (int mt = 0; mt < 4; mt++) {
                int r = wm + mt * 16 + g;
                int ka = kk + 2 * tig;
                uint32_t ah[4], al[4];
                ah[0] = *(uint32_t*)(AsHi + r * RS + ka);
                ah[1] = *(uint32_t*)(AsHi + (r + 8) * RS + ka);
                ah[2] = *(uint32_t*)(AsHi + r * RS + ka + 8);
                ah[3] = *(uint32_t*)(AsHi + (r + 8) * RS + ka + 8);
                al[0] = *(uint32_t*)(AsLo + r * RS + ka);
                al[1] = *(uint32_t*)(AsLo + (r + 8) * RS + ka);
                al[2] = *(uint32_t*)(AsLo + r * RS + ka + 8);
                al[3] = *(uint32_t*)(AsLo + (r + 8) * RS + ka + 8);
#pragma unroll
                for (int nt = 0; nt < 4; nt++) {
                    mma16816(acc[mt][nt], ah, bh[nt]);
                    mma16816(acc[mt][nt], ah, bl[nt]);
                    mma16816(acc[mt][nt], al, bh[nt]);
                }
            }
        }
        __syncthreads();
    }

    // ---- epilogue ----
#pragma unroll
    for (int mt = 0; mt < 4; mt++) {
        int r0 = rowBase + wm + mt * 16 + g;
        int r1 = r0 + 8;
        bool v0 = r0 < M, v1 = r1 < M;
        float dv0 = 0.f, dv1 = 0.f;
        if (mode == 2) {
            if (v0) { float t = dinv[r0]; dv0 = t * t; }
            if (v1) { float t = dinv[r1]; dv1 = t * t; }
        }
#pragma unroll
        for (int nt = 0; nt < 4; nt++) {
            int cn = wn + nt * 8 + 2 * tig;
            float b0 = sBias[cn], b1 = sBias[cn + 1];
            float* c = acc[mt][nt];
            if (mode == 1) {
                if (v0) {
                    float2 o = { leaky(c[0] + b0), leaky(c[1] + b1) };
                    *(float2*)(C0 + (size_t)r0 * D + cn) = o;
                }
                if (v1) {
                    float2 o = { leaky(c[2] + b0), leaky(c[3] + b1) };
                    *(float2*)(C0 + (size_t)r1 * D + cn) = o;
                }
            } else {  // mode 2
                if (v0) {
                    float2 t = { c[0], c[1] };
                    float2 a = { c[0] * dv0 + b0, c[1] * dv0 + b1 };
                    *(float2*)(C0 + (size_t)r0 * D + cn) = t;
                    *(float2*)(C1 + (size_t)r0 * D + cn) = a;
                }
                if (v1) {
                    float2 t = { c[2], c[3] };
                    float2 a = { c[2] * dv1 + b0, c[3] * dv1 + b1 };
                    *(float2*)(C0 + (size_t)r1 * D + cn) = t;
                    *(float2*)(C1 + (size_t)r1 * D + cn) = a;
                }
            }
        }
    }
}

// ---------------------------------------------------------------------------
// Edge index dtype detection + degree helpers
// ---------------------------------------------------------------------------
__global__ void k_detect(const void* __restrict__ ei) {
    const long long* p = (const long long*)ei;
    int ok = 1;
    for (int i = 0; i < 16; i++) {
        long long v = p[i];
        if (v < 0 || v >= NMAX) ok = 0;
    }
    g_idx64 = ok;
}
__device__ __forceinline__ int edge_at(const void* ei, long long idx) {
    if (g_idx64) return (int)((const long long*)ei)[idx];
    return ((const int*)ei)[idx];
}

__global__ void k_init_deg(float* deg, int n) {
    int i = blockIdx.x * blockDim.x + threadIdx.x;
    if (i < n) deg[i] = 1.0f;
}
__global__ void k_count_deg(const void* __restrict__ ei, float* deg, int e) {
    int i = blockIdx.x * blockDim.x + threadIdx.x;
    if (i < e) atomicAdd(&deg[edge_at(ei, (long long)e + i)], 1.0f);
}
__global__ void k_dinv(const float* __restrict__ deg, float* dinv, int n) {
    int i = blockIdx.x * blockDim.x + threadIdx.x;
    if (i < n) dinv[i] = rsqrtf(deg[i]);
}
// Materialize int32 src/dst + per-edge norm (used by both scatter passes)
__global__ void k_prep(const void* __restrict__ ei, const float* __restrict__ dinv,
                       int* __restrict__ s32, int* __restrict__ d32,
                       float* __restrict__ nrm, int E)
{
    int i = blockIdx.x * blockDim.x + threadIdx.x;
    if (i >= E) return;
    int s = edge_at(ei, i);
    int d = edge_at(ei, (long long)E + i);
    s32[i] = s;
    d32[i] = d;
    nrm[i] = dinv[s] * dinv[d];
}

// ---------------------------------------------------------------------------
// Edge scatter: one warp per edge, one red.global.add.v4.f32 per lane.
// ---------------------------------------------------------------------------
__global__ __launch_bounds__(256) void k_scatter(
    const float* __restrict__ t, const int* __restrict__ s32,
    const int* __restrict__ d32, const float* __restrict__ nrm,
    float* __restrict__ agg, int E)
{
    int warp = (blockIdx.x * blockDim.x + threadIdx.x) >> 5;
    int lane = threadIdx.x & 31;
    if (warp >= E) return;
    int s = s32[warp];
    int d = d32[warp];
    float norm = nrm[warp];
    float4 v = *(const float4*)(t + (size_t)s * D + lane * 4);
    v.x *= norm; v.y *= norm; v.z *= norm; v.w *= norm;
    float* p = agg + (size_t)d * D + lane * 4;
    asm volatile("red.global.add.v4.f32 [%0], {%1, %2, %3, %4};"
                 :: "l"(p), "f"(v.x), "f"(v.y), "f"(v.z), "f"(v.w) : "memory");
}

// ---------------------------------------------------------------------------
// Final projection: out[n][0..1] = h3[n] @ W_o2 + b_o2.  One warp per row.
// ---------------------------------------------------------------------------
__global__ __launch_bounds__(256) void k_final(
    const float* __restrict__ h3, const float* __restrict__ W2,
    const float* __restrict__ b2, float* __restrict__ out, int N)
{
    int warp = (blockIdx.x * blockDim.x + threadIdx.x) >> 5;
    int lane = threadIdx.x & 31;
    if (warp >= N) return;
    float4 h = *reinterpret_cast<const float4*>(&h3[(size_t)warp * D + lane * 4]);
    float s0 = 0.f, s1 = 0.f;
    const float* hv = reinterpret_cast<const float*>(&h);
#pragma unroll
    for (int j = 0; j < 4; j++) {
        int k = lane * 4 + j;
        s0 += hv[j] * W2[k * 2 + 0];
        s1 += hv[j] * W2[k * 2 + 1];
    }
#pragma unroll
    for (int off = 16; off; off >>= 1) {
        s0 += __shfl_xor_sync(0xFFFFFFFFu, s0, off);
        s1 += __shfl_xor_sync(0xFFFFFFFFu, s1, off);
    }
    if (lane == 0) {
        out[(size_t)warp * 2 + 0] = s0 + b2[0];
        out[(size_t)warp * 2 + 1] = s1 + b2[1];
    }
}

// ---------------------------------------------------------------------------
// Host launcher
// ---------------------------------------------------------------------------
extern "C" void kernel_launch(void* const* d_in, const int* in_sizes, int n_in,
                              void* d_out, int out_size)
{
    const float* x    = (const float*)d_in[0];
    const void*  ei   = d_in[1];
    const float* W_in = (const float*)d_in[3];
    const float* b_in = (const float*)d_in[4];
    const float* W_g  = (const float*)d_in[5];
    const float* b_g  = (const float*)d_in[6];
    const float* W_o1 = (const float*)d_in[7];
    const float* b_o1 = (const float*)d_in[8];
    const float* W_o2 = (const float*)d_in[9];
    const float* b_o2 = (const float*)d_in[10];
    float*       out  = (float*)d_out;

    const int ND = 239;
    const int N  = in_sizes[0] / ND;
    const int E  = in_sizes[1] / 2;

    float *bufA, *bufB, *bufC, *deg, *dinv, *nrm;
    int *s32, *d32;
    cudaGetSymbolAddress((void**)&bufA, g_bufA);
    cudaGetSymbolAddress((void**)&bufB, g_bufB);
    cudaGetSymbolAddress((void**)&bufC, g_bufC);
    cudaGetSymbolAddress((void**)&deg,  g_deg);
    cudaGetSymbolAddress((void**)&dinv, g_dinv);
    cudaGetSymbolAddress((void**)&nrm,  g_norm);
    cudaGetSymbolAddress((void**)&s32,  g_src32);
    cudaGetSymbolAddress((void**)&d32,  g_dst32);

    const int TB = 256;
    k_detect<<<1, 1>>>(ei);
    k_init_deg<<<(N + TB - 1) / TB, TB>>>(deg, N);
    k_count_deg<<<(E + TB - 1) / TB, TB>>>(ei, deg, E);
    k_dinv<<<(N + TB - 1) / TB, TB>>>(deg, dinv, N);
    k_prep<<<(E + TB - 1) / TB, TB>>>(ei, dinv, s32, d32, nrm, E);

    const int grid = (N + 127) / 128;
    // G1: h0 = leaky(x @ W_in + b_in) -> A
    k_gemm_mma<<<grid, TB>>>(x, W_in, b_in, nullptr, bufA, nullptr, N, ND, ND, 1);
    // G2: t = h0 @ W_g -> B ; agg = t*dinv^2 + b_g -> C
    k_gemm_mma<<<grid, TB>>>(bufA, W_g, b_g, dinv, bufB, bufC, N, D, D, 2);
    k_scatter<<<((size_t)E * 32 + TB - 1) / TB, TB>>>(bufB, s32, d32, nrm, bufC, E);
    // G3: t = h1 @ W_g -> A ; agg -> B
    k_gemm_mma<<<grid, TB>>>(bufC, W_g, b_g, dinv, bufA, bufB, N, D, D, 2);
    k_scatter<<<((size_t)E * 32 + TB - 1) / TB, TB>>>(bufA, s32, d32, nrm, bufB, E);
    // G4: h3 = leaky(h2 @ W_o1 + b_o1) -> C
    k_gemm_mma<<<grid, TB>>>(bufB, W_o1, b_o1, nullptr, bufC, nullptr, N, D, D, 1);
    // out = h3 @ W_o2 + b_o2
    k_final<<<((size_t)N * 32 + TB - 1) / TB, TB>>>(bufC, W_o2, b_o2, out, N);
}

// round 9
// speedup vs baseline: 1.4975x; 1.1205x over previous
#include <cuda_runtime.h>
#include <cuda_bf16.h>
#include <cstdint>
#include <math.h>

#define NMAX 100000
#define EMAX 640000
#define D    128

// Scratch
__device__ float g_bufA[(size_t)NMAX * D];
__device__ float g_bufB[(size_t)NMAX * D];
__device__ float g_bufC[(size_t)NMAX * D];
__device__ float g_dinv[NMAX];
__device__ int   g_indeg[NMAX];
__device__ int   g_csr[NMAX + 1];
__device__ int   g_cursor[NMAX];
__device__ int   g_part[512];
__device__ int   g_srcS[EMAX];
__device__ float g_normS[EMAX];
__device__ int   g_idx64;

__device__ __forceinline__ float leaky(float v) { return v >= 0.f ? v : 0.01f * v; }

// ---------------------------------------------------------------------------
// m16n8k16 bf16 MMA (portable HMMA path)
// ---------------------------------------------------------------------------
__device__ __forceinline__ void mma16816(float* c, const uint32_t* a, const uint32_t* b) {
    asm volatile(
        "mma.sync.aligned.m16n8k16.row.col.f32.bf16.bf16.f32 "
        "{%0,%1,%2,%3}, {%4,%5,%6,%7}, {%8,%9}, {%0,%1,%2,%3};"
        : "+f"(c[0]), "+f"(c[1]), "+f"(c[2]), "+f"(c[3])
        : "r"(a[0]), "r"(a[1]), "r"(a[2]), "r"(a[3]), "r"(b[0]), "r"(b[1]));
}

__device__ __forceinline__ uint32_t pack_hi(float a0, float a1) {
    __nv_bfloat16 h0 = __float2bfloat16(a0), h1 = __float2bfloat16(a1);
    return (uint32_t)__bfloat16_as_ushort(h0) | ((uint32_t)__bfloat16_as_ushort(h1) << 16);
}
__device__ __forceinline__ uint32_t pack_lo(float a0, float a1) {
    __nv_bfloat16 h0 = __float2bfloat16(a0), h1 = __float2bfloat16(a1);
    __nv_bfloat16 l0 = __float2bfloat16(a0 - __bfloat162float(h0));
    __nv_bfloat16 l1 = __float2bfloat16(a1 - __bfloat162float(h1));
    return (uint32_t)__bfloat16_as_ushort(l0) | ((uint32_t)__bfloat16_as_ushort(l1) << 16);
}

// ---------------------------------------------------------------------------
// GEMM: C = A[M,K] @ W[K,128].  128x128 block tile, 8 warps, reg-prefetch.
// mode 0: C0 = acc (raw)
// mode 1: C0 = leaky(acc + bias)
// ---------------------------------------------------------------------------
#define RS 40

struct Frag { uint32_t aHi[8], aLo[8], bHi[8], bLo[8]; };

__device__ __forceinline__ void prefetch(
    Frag& f, const float* __restrict__ A, const float* __restrict__ W,
    int rowBase, int M, int K, int lda, int k0, int tid)
{
#pragma unroll
    for (int i = 0; i < 8; i++) {
        int w = tid + i * 256;
        int row = w >> 4, kw = w & 15;
        int grow = rowBase + row, gk = k0 + kw * 2;
        float a0 = 0.f, a1 = 0.f;
        if (grow < M) {
            const float* ap = A + (size_t)grow * lda;
            if (gk < K)     a0 = ap[gk];
            if (gk + 1 < K) a1 = ap[gk + 1];
        }
        f.aHi[i] = pack_hi(a0, a1);
        f.aLo[i] = pack_lo(a0, a1);
    }
#pragma unroll
    for (int i = 0; i < 8; i++) {
        int w = tid + i * 256;
        int n = w & 127, kw = w >> 7;
        int gk = k0 + kw * 2;
        float b0 = (gk < K)     ? W[(size_t)gk * D + n]       : 0.f;
        float b1 = (gk + 1 < K) ? W[(size_t)(gk + 1) * D + n] : 0.f;
        f.bHi[i] = pack_hi(b0, b1);
        f.bLo[i] = pack_lo(b0, b1);
    }
}

__global__ __launch_bounds__(256, 2) void k_gemm_mma(
    const float* __restrict__ A, const float* __restrict__ W,
    const float* __restrict__ bias,
    float* __restrict__ C0,
    int M, int K, int lda, int mode)
{
    __shared__ float sBias[128];
    __shared__ __align__(16) __nv_bfloat16 AsHi[128 * RS];
    __shared__ __align__(16) __nv_bfloat16 AsLo[128 * RS];
    __shared__ __align__(16) __nv_bfloat16 BsHi[128 * RS];
    __shared__ __align__(16) __nv_bfloat16 BsLo[128 * RS];

    const int tid  = threadIdx.x;
    const int wid  = tid >> 5;
    const int lane = tid & 31;
    const int g    = lane >> 2;
    const int tig  = lane & 3;
    const int wm   = (wid >> 2) * 64;
    const int wn   = (wid & 3) * 32;
    const int rowBase = blockIdx.x * 128;

    if (mode == 1 && tid < 128) sBias[tid] = bias[tid];

    float acc[4][4][4];
#pragma unroll
    for (int mt = 0; mt < 4; mt++)
#pragma unroll
        for (int nt = 0; nt < 4; nt++)
#pragma unroll
            for (int j = 0; j < 4; j++) acc[mt][nt][j] = 0.f;

    const int nStages = (K + 31) >> 5;
    Frag f;
    prefetch(f, A, W, rowBase, M, K, lda, 0, tid);

    for (int st = 0; st < nStages; st++) {
#pragma unroll
        for (int i = 0; i < 8; i++) {
            int w = tid + i * 256;
            int row = w >> 4, kw = w & 15;
            int so = row * RS + kw * 2;
            *(uint32_t*)(AsHi + so) = f.aHi[i];
            *(uint32_t*)(AsLo + so) = f.aLo[i];
            int n = w & 127, kb = (w >> 7) * 2;
            int sb = n * RS + kb;
            *(uint32_t*)(BsHi + sb) = f.bHi[i];
            *(uint32_t*)(BsLo + sb) = f.bLo[i];
        }
        __syncthreads();

        if (st + 1 < nStages)
            prefetch(f, A, W, rowBase, M, K, lda, (st + 1) << 5, tid);

#pragma unroll
        for (int kk = 0; kk < 32; kk += 16) {
            uint32_t bh[4][2], bl[4][2];
#pragma unroll
            for (int nt = 0; nt < 4; nt++) {
                int n = wn + nt * 8 + g;
                int kb = kk + 2 * tig;
                bh[nt][0] = *(uint32_t*)(BsHi + n * RS + kb);
                bh[nt][1] = *(uint32_t*)(BsHi + n * RS + kb + 8);
                bl[nt][0] = *(uint32_t*)(BsLo + n * RS + kb);
                bl[nt][1] = *(uint32_t*)(BsLo + n * RS + kb + 8);
            }
#pragma unroll
            for (int mt = 0; mt < 4; mt++) {
                int r = wm + mt * 16 + g;
                int ka = kk + 2 * tig;
                uint32_t ah[4], al[4];
                ah[0] = *(uint32_t*)(AsHi + r * RS + ka);
                ah[1] = *(uint32_t*)(AsHi + (r + 8) * RS + ka);
                ah[2] = *(uint32_t*)(AsHi + r * RS + ka + 8);
                ah[3] = *(uint32_t*)(AsHi + (r + 8) * RS + ka + 8);
                al[0] = *(uint32_t*)(AsLo + r * RS + ka);
                al[1] = *(uint32_t*)(AsLo + (r + 8) * RS + ka);
                al[2] = *(uint32_t*)(AsLo + r * RS + ka + 8);
                al[3] = *(uint32_t*)(AsLo + (r + 8) * RS + ka + 8);
#pragma unroll
                for (int nt = 0; nt < 4; nt++) {
                    mma16816(acc[mt][nt], ah, bh[nt]);
                    mma16816(acc[mt][nt], ah, bl[nt]);
                    mma16816(acc[mt][nt], al, bh[nt]);
                }
            }
        }
        __syncthreads();
    }

#pragma unroll
    for (int mt = 0; mt < 4; mt++) {
        int r0 = rowBase + wm + mt * 16 + g;
        int r1 = r0 + 8;
        bool v0 = r0 < M, v1 = r1 < M;
#pragma unroll
        for (int nt = 0; nt < 4; nt++) {
            int cn = wn + nt * 8 + 2 * tig;
            float* c = acc[mt][nt];
            if (mode == 1) {
                float b0 = sBias[cn], b1 = sBias[cn + 1];
                if (v0) {
                    float2 o = { leaky(c[0] + b0), leaky(c[1] + b1) };
                    *(float2*)(C0 + (size_t)r0 * D + cn) = o;
                }
                if (v1) {
                    float2 o = { leaky(c[2] + b0), leaky(c[3] + b1) };
                    *(float2*)(C0 + (size_t)r1 * D + cn) = o;
                }
            } else {
                if (v0) { float2 o = { c[0], c[1] }; *(float2*)(C0 + (size_t)r0 * D + cn) = o; }
                if (v1) { float2 o = { c[2], c[3] }; *(float2*)(C0 + (size_t)r1 * D + cn) = o; }
            }
        }
    }
}

// ---------------------------------------------------------------------------
// Edge dtype detection + CSR build
// ---------------------------------------------------------------------------
__global__ void k_detect(const void* __restrict__ ei) {
    const long long* p = (const long long*)ei;
    int ok = 1;
    for (int i = 0; i < 16; i++) {
        long long v = p[i];
        if (v < 0 || v >= NMAX) ok = 0;
    }
    g_idx64 = ok;
}
__device__ __forceinline__ int edge_at(const void* ei, long long idx) {
    if (g_idx64) return (int)((const long long*)ei)[idx];
    return ((const int*)ei)[idx];
}

__global__ void k_zero(int* indeg, int n) {
    int i = blockIdx.x * blockDim.x + threadIdx.x;
    if (i < n) indeg[i] = 0;
}
__global__ void k_count(const void* __restrict__ ei, int* indeg, int e) {
    int i = blockIdx.x * blockDim.x + threadIdx.x;
    if (i < e) atomicAdd(&indeg[edge_at(ei, (long long)e + i)], 1);
}
__global__ void k_dinv(const int* __restrict__ indeg, float* dinv, int n) {
    int i = blockIdx.x * blockDim.x + threadIdx.x;
    if (i < n) dinv[i] = rsqrtf(1.0f + (float)indeg[i]);
}

// Block-level exclusive scan of indeg -> csr (per-block), block sums -> part
__global__ void k_scan1(const int* __restrict__ indeg, int* __restrict__ csr,
                        int* __restrict__ part, int n)
{
    __shared__ int sh[256];
    int t = threadIdx.x;
    int i = blockIdx.x * 256 + t;
    int v = (i < n) ? indeg[i] : 0;
    sh[t] = v;
    __syncthreads();
#pragma unroll
    for (int off = 1; off < 256; off <<= 1) {
        int x = (t >= off) ? sh[t - off] : 0;
        __syncthreads();
        sh[t] += x;
        __syncthreads();
    }
    if (i < n) csr[i] = sh[t] - v;           // exclusive within block
    if (t == 255) part[blockIdx.x] = sh[t];  // inclusive block total
}

// Scan the (<=512) block totals in one block
__global__ void k_scan2(int* __restrict__ part, int nb) {
    __shared__ int sh[512];
    int t = threadIdx.x;
    int v = (t < nb) ? part[t] : 0;
    sh[t] = v;
    __syncthreads();
#pragma unroll
    for (int off = 1; off < 512; off <<= 1) {
        int x = (t >= off) ? sh[t - off] : 0;
        __syncthreads();
        sh[t] += x;
        __syncthreads();
    }
    if (t < nb) part[t] = sh[t] - v;  // exclusive
}

// Add block offsets; zero cursors; set csr[n] = E
__global__ void k_scan3(int* __restrict__ csr, const int* __restrict__ part,
                        const int* __restrict__ indeg, int* __restrict__ cursor, int n)
{
    int i = blockIdx.x * blockDim.x + threadIdx.x;
    if (i >= n) return;
    int base = csr[i] + part[i >> 8];
    csr[i] = base;
    cursor[i] = 0;
    if (i == n - 1) csr[n] = base + indeg[i];
}

// Fill dst-sorted edge arrays
__global__ void k_fill(const void* __restrict__ ei, const float* __restrict__ dinv,
                       const int* __restrict__ csr, int* __restrict__ cursor,
                       int* __restrict__ srcS, float* __restrict__ normS, int E)
{
    int i = blockIdx.x * blockDim.x + threadIdx.x;
    if (i >= E) return;
    int s = edge_at(ei, i);
    int d = edge_at(ei, (long long)E + i);
    int p = csr[d] + atomicAdd(&cursor[d], 1);
    srcS[p] = s;
    normS[p] = dinv[s] * dinv[d];
}

// ---------------------------------------------------------------------------
// Gather aggregation: one warp per dst node.  No atomics.
// agg[n] = t[n]*dinv[n]^2 + bias + sum_{e in CSR[n]} norm[e] * t[src[e]]
// ---------------------------------------------------------------------------
__global__ __launch_bounds__(256) void k_gather(
    const float* __restrict__ t, const int* __restrict__ csr,
    const int* __restrict__ srcS, const float* __restrict__ normS,
    const float* __restrict__ dinv, const float* __restrict__ bias,
    float* __restrict__ agg, int N)
{
    int warp = (blockIdx.x * blockDim.x + threadIdx.x) >> 5;
    int lane = threadIdx.x & 31;
    if (warp >= N) return;
    int beg = csr[warp], end = csr[warp + 1];
    float dv = dinv[warp];
    float dv2 = dv * dv;
    float4 b4 = *(const float4*)(bias + lane * 4);
    float4 a  = *(const float4*)(t + (size_t)warp * D + lane * 4);
    float4 acc;
    acc.x = a.x * dv2 + b4.x;
    acc.y = a.y * dv2 + b4.y;
    acc.z = a.z * dv2 + b4.z;
    acc.w = a.w * dv2 + b4.w;
    for (int e = beg; e < end; e++) {
        int s = srcS[e];            // broadcast across warp
        float nm = normS[e];
        float4 v = *(const float4*)(t + (size_t)s * D + lane * 4);
        acc.x += nm * v.x;
        acc.y += nm * v.y;
        acc.z += nm * v.z;
        acc.w += nm * v.w;
    }
    *(float4*)(agg + (size_t)warp * D + lane * 4) = acc;
}

// ---------------------------------------------------------------------------
// Final projection
// ---------------------------------------------------------------------------
__global__ __launch_bounds__(256) void k_final(
    const float* __restrict__ h3, const float* __restrict__ W2,
    const float* __restrict__ b2, float* __restrict__ out, int N)
{
    int warp = (blockIdx.x * blockDim.x + threadIdx.x) >> 5;
    int lane = threadIdx.x & 31;
    if (warp >= N) return;
    float4 h = *reinterpret_cast<const float4*>(&h3[(size_t)warp * D + lane * 4]);
    float s0 = 0.f, s1 = 0.f;
    const float* hv = reinterpret_cast<const float*>(&h);
#pragma unroll
    for (int j = 0; j < 4; j++) {
        int k = lane * 4 + j;
        s0 += hv[j] * W2[k * 2 + 0];
        s1 += hv[j] * W2[k * 2 + 1];
    }
#pragma unroll
    for (int off = 16; off; off >>= 1) {
        s0 += __shfl_xor_sync(0xFFFFFFFFu, s0, off);
        s1 += __shfl_xor_sync(0xFFFFFFFFu, s1, off);
    }
    if (lane == 0) {
        out[(size_t)warp * 2 + 0] = s0 + b2[0];
        out[(size_t)warp * 2 + 1] = s1 + b2[1];
    }
}

// ---------------------------------------------------------------------------
// Host launcher
// ---------------------------------------------------------------------------
extern "C" void kernel_launch(void* const* d_in, const int* in_sizes, int n_in,
                              void* d_out, int out_size)
{
    const float* x    = (const float*)d_in[0];
    const void*  ei   = d_in[1];
    const float* W_in = (const float*)d_in[3];
    const float* b_in = (const float*)d_in[4];
    const float* W_g  = (const float*)d_in[5];
    const float* b_g  = (const float*)d_in[6];
    const float* W_o1 = (const float*)d_in[7];
    const float* b_o1 = (const float*)d_in[8];
    const float* W_o2 = (const float*)d_in[9];
    const float* b_o2 = (const float*)d_in[10];
    float*       out  = (float*)d_out;

    const int ND = 239;
    const int N  = in_sizes[0] / ND;
    const int E  = in_sizes[1] / 2;

    float *bufA, *bufB, *bufC, *dinv, *normS;
    int *indeg, *csr, *cursor, *part, *srcS;
    cudaGetSymbolAddress((void**)&bufA,  g_bufA);
    cudaGetSymbolAddress((void**)&bufB,  g_bufB);
    cudaGetSymbolAddress((void**)&bufC,  g_bufC);
    cudaGetSymbolAddress((void**)&dinv,  g_dinv);
    cudaGetSymbolAddress((void**)&indeg, g_indeg);
    cudaGetSymbolAddress((void**)&csr,   g_csr);
    cudaGetSymbolAddress((void**)&cursor,g_cursor);
    cudaGetSymbolAddress((void**)&part,  g_part);
    cudaGetSymbolAddress((void**)&srcS,  g_srcS);
    cudaGetSymbolAddress((void**)&normS, g_normS);

    const int TB = 256;
    const int nBlk = (N + 255) / 256;

    k_detect<<<1, 1>>>(ei);
    k_zero<<<nBlk, TB>>>(indeg, N);
    k_count<<<(E + TB - 1) / TB, TB>>>(ei, indeg, E);
    k_dinv<<<nBlk, TB>>>(indeg, dinv, N);
    k_scan1<<<nBlk, TB>>>(indeg, csr, part, N);
    k_scan2<<<1, 512>>>(part, nBlk);
    k_scan3<<<nBlk, TB>>>(csr, part, indeg, cursor, N);
    k_fill<<<(E + TB - 1) / TB, TB>>>(ei, dinv, csr, cursor, srcS, normS, E);

    const int grid = (N + 127) / 128;
    const int gGrid = ((size_t)N * 32 + TB - 1) / TB;
    // G1: h0 = leaky(x @ W_in + b_in) -> A
    k_gemm_mma<<<grid, TB>>>(x, W_in, b_in, bufA, N, ND, ND, 1);
    // conv1: t = h0 @ W_g -> B ; gather -> C
    k_gemm_mma<<<grid, TB>>>(bufA, W_g, nullptr, bufB, N, D, D, 0);
    k_gather<<<gGrid, TB>>>(bufB, csr, srcS, normS, dinv, b_g, bufC, N);
    // conv2: t = h1 @ W_g -> A ; gather -> B
    k_gemm_mma<<<grid, TB>>>(bufC, W_g, nullptr, bufA, N, D, D, 0);
    k_gather<<<gGrid, TB>>>(bufA, csr, srcS, normS, dinv, b_g, bufB, N);
    // G4: h3 = leaky(h2 @ W_o1 + b_o1) -> C
    k_gemm_mma<<<grid, TB>>>(bufB, W_o1, b_o1, bufC, N, D, D, 1);
    // out
    k_final<<<gGrid, TB>>>(bufC, W_o2, b_o2, out, N);
}

// round 10
// speedup vs baseline: 1.5339x; 1.0243x over previous
#include <cuda_runtime.h>
#include <cuda_bf16.h>
#include <cstdint>
#include <math.h>

#define NMAX 100000
#define EMAX 640000
#define D    128

// Scratch
__device__ float g_bufA[(size_t)NMAX * D];
__device__ float g_bufB[(size_t)NMAX * D];
__device__ float g_bufC[(size_t)NMAX * D];
__device__ float g_dinv[NMAX];
__device__ int   g_indeg[NMAX];
__device__ int   g_csr[NMAX + 1];
__device__ int   g_cursor[NMAX];
__device__ int   g_part[512];
__device__ int   g_srcS[EMAX];
__device__ float g_normS[EMAX];
__device__ int   g_idx64;

__device__ __forceinline__ float leaky(float v) { return v >= 0.f ? v : 0.01f * v; }

// ---------------------------------------------------------------------------
// m16n8k16 bf16 MMA + ldmatrix (portable paths, plain sm_103 target)
// ---------------------------------------------------------------------------
__device__ __forceinline__ void mma16816(float* c, const uint32_t* a, const uint32_t* b) {
    asm volatile(
        "mma.sync.aligned.m16n8k16.row.col.f32.bf16.bf16.f32 "
        "{%0,%1,%2,%3}, {%4,%5,%6,%7}, {%8,%9}, {%0,%1,%2,%3};"
        : "+f"(c[0]), "+f"(c[1]), "+f"(c[2]), "+f"(c[3])
        : "r"(a[0]), "r"(a[1]), "r"(a[2]), "r"(a[3]), "r"(b[0]), "r"(b[1]));
}

__device__ __forceinline__ void ldsm4(uint32_t* r, uint32_t addr) {
    asm volatile("ldmatrix.sync.aligned.m8n8.x4.shared.b16 {%0,%1,%2,%3}, [%4];"
                 : "=r"(r[0]), "=r"(r[1]), "=r"(r[2]), "=r"(r[3]) : "r"(addr));
}

__device__ __forceinline__ uint32_t pack_hi(float a0, float a1) {
    __nv_bfloat16 h0 = __float2bfloat16(a0), h1 = __float2bfloat16(a1);
    return (uint32_t)__bfloat16_as_ushort(h0) | ((uint32_t)__bfloat16_as_ushort(h1) << 16);
}
__device__ __forceinline__ uint32_t pack_lo(float a0, float a1) {
    __nv_bfloat16 h0 = __float2bfloat16(a0), h1 = __float2bfloat16(a1);
    __nv_bfloat16 l0 = __float2bfloat16(a0 - __bfloat162float(h0));
    __nv_bfloat16 l1 = __float2bfloat16(a1 - __bfloat162float(h1));
    return (uint32_t)__bfloat16_as_ushort(l0) | ((uint32_t)__bfloat16_as_ushort(l1) << 16);
}

// ---------------------------------------------------------------------------
// GEMM: C = A[M,K] @ W[K,128].  128x128 block tile, 8 warps, reg-prefetch,
// ldmatrix fragment loads.  mode 0: C0 = acc.  mode 1: C0 = leaky(acc + bias)
// ---------------------------------------------------------------------------
#define RS 40  // smem row stride in halves (80B: 8 consecutive rows -> 8 banks)

struct Frag { uint32_t aHi[8], aLo[8], bHi[8], bLo[8]; };

__device__ __forceinline__ void prefetch(
    Frag& f, const float* __restrict__ A, const float* __restrict__ W,
    int rowBase, int M, int K, int lda, int k0, int tid)
{
#pragma unroll
    for (int i = 0; i < 8; i++) {
        int w = tid + i * 256;
        int row = w >> 4, kw = w & 15;
        int grow = rowBase + row, gk = k0 + kw * 2;
        float a0 = 0.f, a1 = 0.f;
        if (grow < M) {
            const float* ap = A + (size_t)grow * lda;
            if (gk < K)     a0 = ap[gk];
            if (gk + 1 < K) a1 = ap[gk + 1];
        }
        f.aHi[i] = pack_hi(a0, a1);
        f.aLo[i] = pack_lo(a0, a1);
    }
#pragma unroll
    for (int i = 0; i < 8; i++) {
        int w = tid + i * 256;
        int n = w & 127, kw = w >> 7;
        int gk = k0 + kw * 2;
        float b0 = (gk < K)     ? W[(size_t)gk * D + n]       : 0.f;
        float b1 = (gk + 1 < K) ? W[(size_t)(gk + 1) * D + n] : 0.f;
        f.bHi[i] = pack_hi(b0, b1);
        f.bLo[i] = pack_lo(b0, b1);
    }
}

__global__ __launch_bounds__(256, 2) void k_gemm_mma(
    const float* __restrict__ A, const float* __restrict__ W,
    const float* __restrict__ bias,
    float* __restrict__ C0,
    int M, int K, int lda, int mode)
{
    __shared__ float sBias[128];
    __shared__ __align__(16) __nv_bfloat16 AsHi[128 * RS];
    __shared__ __align__(16) __nv_bfloat16 AsLo[128 * RS];
    __shared__ __align__(16) __nv_bfloat16 BsHi[128 * RS];
    __shared__ __align__(16) __nv_bfloat16 BsLo[128 * RS];

    const int tid  = threadIdx.x;
    const int wid  = tid >> 5;
    const int lane = tid & 31;
    const int g    = lane >> 2;
    const int tig  = lane & 3;
    const int wm   = (wid >> 2) * 64;
    const int wn   = (wid & 3) * 32;
    const int rowBase = blockIdx.x * 128;

    if (mode == 1 && tid < 128) sBias[tid] = bias[tid];

    // ldmatrix address precompute (byte offsets at kk=0)
    const uint32_t aBaseH = (uint32_t)__cvta_generic_to_shared(AsHi);
    const uint32_t aBaseL = (uint32_t)__cvta_generic_to_shared(AsLo);
    const uint32_t bBaseH = (uint32_t)__cvta_generic_to_shared(BsHi);
    const uint32_t bBaseL = (uint32_t)__cvta_generic_to_shared(BsLo);
    const int aRow  = wm + (lane & 15);
    const int aColH = (lane >> 4) * 8;             // halves
    uint32_t aOff[4];
#pragma unroll
    for (int mt = 0; mt < 4; mt++)
        aOff[mt] = (uint32_t)(((aRow + mt * 16) * RS + aColH) * 2);
    const int bQ  = lane >> 3, bL7 = lane & 7;
    const int bNo = ((bQ >> 1) & 1) * 8 + bL7;
    const int bKo = (bQ & 1) * 8;                  // halves
    uint32_t bOff[2];
#pragma unroll
    for (int p = 0; p < 2; p++)
        bOff[p] = (uint32_t)(((wn + p * 16 + bNo) * RS + bKo) * 2);

    float acc[4][4][4];
#pragma unroll
    for (int mt = 0; mt < 4; mt++)
#pragma unroll
        for (int nt = 0; nt < 4; nt++)
#pragma unroll
            for (int j = 0; j < 4; j++) acc[mt][nt][j] = 0.f;

    const int nStages = (K + 31) >> 5;
    Frag f;
    prefetch(f, A, W, rowBase, M, K, lda, 0, tid);

    for (int st = 0; st < nStages; st++) {
        // ---- commit prefetched regs to smem (short critical section) ----
#pragma unroll
        for (int i = 0; i < 8; i++) {
            int w = tid + i * 256;
            int row = w >> 4, kw = w & 15;
            int so = row * RS + kw * 2;
            *(uint32_t*)(AsHi + so) = f.aHi[i];
            *(uint32_t*)(AsLo + so) = f.aLo[i];
            int n = w & 127, kb = (w >> 7) * 2;
            int sb = n * RS + kb;
            *(uint32_t*)(BsHi + sb) = f.bHi[i];
            *(uint32_t*)(BsLo + sb) = f.bLo[i];
        }
        __syncthreads();

        // ---- issue next-stage global loads (overlap with mma below) ----
        if (st + 1 < nStages)
            prefetch(f, A, W, rowBase, M, K, lda, (st + 1) << 5, tid);

        // ---- compute: two k16 sub-steps, ldmatrix fragments ----
#pragma unroll
        for (int kkB = 0; kkB < 64; kkB += 32) {   // byte offset of k16 substep
            uint32_t bh[2][4], bl[2][4];
            ldsm4(bh[0], bBaseH + bOff[0] + kkB);
            ldsm4(bh[1], bBaseH + bOff[1] + kkB);
            ldsm4(bl[0], bBaseL + bOff[0] + kkB);
            ldsm4(bl[1], bBaseL + bOff[1] + kkB);
#pragma unroll
            for (int mt = 0; mt < 4; mt++) {
                uint32_t ah[4], al[4];
                ldsm4(ah, aBaseH + aOff[mt] + kkB);
                ldsm4(al, aBaseL + aOff[mt] + kkB);
#pragma unroll
                for (int nt = 0; nt < 4; nt++) {
                    const uint32_t* bhp = &bh[nt >> 1][(nt & 1) * 2];
                    const uint32_t* blp = &bl[nt >> 1][(nt & 1) * 2];
                    mma16816(acc[mt][nt], ah, bhp);
                    mma16816(acc[mt][nt], ah, blp);
                    mma16816(acc[mt][nt], al, bhp);
                }
            }
        }
        __syncthreads();
    }

    // ---- epilogue ----
#pragma unroll
    for (int mt = 0; mt < 4; mt++) {
        int r0 = rowBase + wm + mt * 16 + g;
        int r1 = r0 + 8;
        bool v0 = r0 < M, v1 = r1 < M;
#pragma unroll
        for (int nt = 0; nt < 4; nt++) {
            int cn = wn + nt * 8 + 2 * tig;
            float* c = acc[mt][nt];
            if (mode == 1) {
                float b0 = sBias[cn], b1 = sBias[cn + 1];
                if (v0) {
                    float2 o = { leaky(c[0] + b0), leaky(c[1] + b1) };
                    *(float2*)(C0 + (size_t)r0 * D + cn) = o;
                }
                if (v1) {
                    float2 o = { leaky(c[2] + b0), leaky(c[3] + b1) };
                    *(float2*)(C0 + (size_t)r1 * D + cn) = o;
                }
            } else {
                if (v0) { float2 o = { c[0], c[1] }; *(float2*)(C0 + (size_t)r0 * D + cn) = o; }
                if (v1) { float2 o = { c[2], c[3] }; *(float2*)(C0 + (size_t)r1 * D + cn) = o; }
            }
        }
    }
}

// ---------------------------------------------------------------------------
// Edge dtype detection + CSR build
// ---------------------------------------------------------------------------
__global__ void k_detect(const void* __restrict__ ei) {
    const long long* p = (const long long*)ei;
    int ok = 1;
    for (int i = 0; i < 16; i++) {
        long long v = p[i];
        if (v < 0 || v >= NMAX) ok = 0;
    }
    g_idx64 = ok;
}
__device__ __forceinline__ int edge_at(const void* ei, long long idx) {
    if (g_idx64) return (int)((const long long*)ei)[idx];
    return ((const int*)ei)[idx];
}

__global__ void k_zero(int* indeg, int n) {
    int i = blockIdx.x * blockDim.x + threadIdx.x;
    if (i < n) indeg[i] = 0;
}
__global__ void k_count(const void* __restrict__ ei, int* indeg, int e) {
    int i = blockIdx.x * blockDim.x + threadIdx.x;
    if (i < e) atomicAdd(&indeg[edge_at(ei, (long long)e + i)], 1);
}
__global__ void k_dinv(const int* __restrict__ indeg, float* dinv, int n) {
    int i = blockIdx.x * blockDim.x + threadIdx.x;
    if (i < n) dinv[i] = rsqrtf(1.0f + (float)indeg[i]);
}

__global__ void k_scan1(const int* __restrict__ indeg, int* __restrict__ csr,
                        int* __restrict__ part, int n)
{
    __shared__ int sh[256];
    int t = threadIdx.x;
    int i = blockIdx.x * 256 + t;
    int v = (i < n) ? indeg[i] : 0;
    sh[t] = v;
    __syncthreads();
#pragma unroll
    for (int off = 1; off < 256; off <<= 1) {
        int x = (t >= off) ? sh[t - off] : 0;
        __syncthreads();
        sh[t] += x;
        __syncthreads();
    }
    if (i < n) csr[i] = sh[t] - v;
    if (t == 255) part[blockIdx.x] = sh[t];
}

__global__ void k_scan2(int* __restrict__ part, int nb) {
    __shared__ int sh[512];
    int t = threadIdx.x;
    int v = (t < nb) ? part[t] : 0;
    sh[t] = v;
    __syncthreads();
#pragma unroll
    for (int off = 1; off < 512; off <<= 1) {
        int x = (t >= off) ? sh[t - off] : 0;
        __syncthreads();
        sh[t] += x;
        __syncthreads();
    }
    if (t < nb) part[t] = sh[t] - v;
}

__global__ void k_scan3(int* __restrict__ csr, const int* __restrict__ part,
                        const int* __restrict__ indeg, int* __restrict__ cursor, int n)
{
    int i = blockIdx.x * blockDim.x + threadIdx.x;
    if (i >= n) return;
    int base = csr[i] + part[i >> 8];
    csr[i] = base;
    cursor[i] = 0;
    if (i == n - 1) csr[n] = base + indeg[i];
}

__global__ void k_fill(const void* __restrict__ ei, const float* __restrict__ dinv,
                       const int* __restrict__ csr, int* __restrict__ cursor,
                       int* __restrict__ srcS, float* __restrict__ normS, int E)
{
    int i = blockIdx.x * blockDim.x + threadIdx.x;
    if (i >= E) return;
    int s = edge_at(ei, i);
    int d = edge_at(ei, (long long)E + i);
    int p = csr[d] + atomicAdd(&cursor[d], 1);
    srcS[p] = s;
    normS[p] = dinv[s] * dinv[d];
}

// ---------------------------------------------------------------------------
// Gather aggregation: one warp per dst node.  No atomics.
// ---------------------------------------------------------------------------
__global__ __launch_bounds__(256) void k_gather(
    const float* __restrict__ t, const int* __restrict__ csr,
    const int* __restrict__ srcS, const float* __restrict__ normS,
    const float* __restrict__ dinv, const float* __restrict__ bias,
    float* __restrict__ agg, int N)
{
    int warp = (blockIdx.x * blockDim.x + threadIdx.x) >> 5;
    int lane = threadIdx.x & 31;
    if (warp >= N) return;
    int beg = csr[warp], end = csr[warp + 1];
    float dv = dinv[warp];
    float dv2 = dv * dv;
    float4 b4 = *(const float4*)(bias + lane * 4);
    float4 a  = *(const float4*)(t + (size_t)warp * D + lane * 4);
    float4 acc;
    acc.x = a.x * dv2 + b4.x;
    acc.y = a.y * dv2 + b4.y;
    acc.z = a.z * dv2 + b4.z;
    acc.w = a.w * dv2 + b4.w;
    for (int e = beg; e < end; e++) {
        int s = srcS[e];
        float nm = normS[e];
        float4 v = *(const float4*)(t + (size_t)s * D + lane * 4);
        acc.x += nm * v.x;
        acc.y += nm * v.y;
        acc.z += nm * v.z;
        acc.w += nm * v.w;
    }
    *(float4*)(agg + (size_t)warp * D + lane * 4) = acc;
}

// ---------------------------------------------------------------------------
// Final projection
// ---------------------------------------------------------------------------
__global__ __launch_bounds__(256) void k_final(
    const float* __restrict__ h3, const float* __restrict__ W2,
    const float* __restrict__ b2, float* __restrict__ out, int N)
{
    int warp = (blockIdx.x * blockDim.x + threadIdx.x) >> 5;
    int lane = threadIdx.x & 31;
    if (warp >= N) return;
    float4 h = *reinterpret_cast<const float4*>(&h3[(size_t)warp * D + lane * 4]);
    float s0 = 0.f, s1 = 0.f;
    const float* hv = reinterpret_cast<const float*>(&h);
#pragma unroll
    for (int j = 0; j < 4; j++) {
        int k = lane * 4 + j;
        s0 += hv[j] * W2[k * 2 + 0];
        s1 += hv[j] * W2[k * 2 + 1];
    }
#pragma unroll
    for (int off = 16; off; off >>= 1) {
        s0 += __shfl_xor_sync(0xFFFFFFFFu, s0, off);
        s1 += __shfl_xor_sync(0xFFFFFFFFu, s1, off);
    }
    if (lane == 0) {
        out[(size_t)warp * 2 + 0] = s0 + b2[0];
        out[(size_t)warp * 2 + 1] = s1 + b2[1];
    }
}

// ---------------------------------------------------------------------------
// Host launcher
// ---------------------------------------------------------------------------
extern "C" void kernel_launch(void* const* d_in, const int* in_sizes, int n_in,
                              void* d_out, int out_size)
{
    const float* x    = (const float*)d_in[0];
    const void*  ei   = d_in[1];
    const float* W_in = (const float*)d_in[3];
    const float* b_in = (const float*)d_in[4];
    const float* W_g  = (const float*)d_in[5];
    const float* b_g  = (const float*)d_in[6];
    const float* W_o1 = (const float*)d_in[7];
    const float* b_o1 = (const float*)d_in[8];
    const float* W_o2 = (const float*)d_in[9];
    const float* b_o2 = (const float*)d_in[10];
    float*       out  = (float*)d_out;

    const int ND = 239;
    const int N  = in_sizes[0] / ND;
    const int E  = in_sizes[1] / 2;

    float *bufA, *bufB, *bufC, *dinv, *normS;
    int *indeg, *csr, *cursor, *part, *srcS;
    cudaGetSymbolAddress((void**)&bufA,  g_bufA);
    cudaGetSymbolAddress((void**)&bufB,  g_bufB);
    cudaGetSymbolAddress((void**)&bufC,  g_bufC);
    cudaGetSymbolAddress((void**)&dinv,  g_dinv);
    cudaGetSymbolAddress((void**)&indeg, g_indeg);
    cudaGetSymbolAddress((void**)&csr,   g_csr);
    cudaGetSymbolAddress((void**)&cursor,g_cursor);
    cudaGetSymbolAddress((void**)&part,  g_part);
    cudaGetSymbolAddress((void**)&srcS,  g_srcS);
    cudaGetSymbolAddress((void**)&normS, g_normS);

    const int TB = 256;
    const int nBlk = (N + 255) / 256;

    k_detect<<<1, 1>>>(ei);
    k_zero<<<nBlk, TB>>>(indeg, N);
    k_count<<<(E + TB - 1) / TB, TB>>>(ei, indeg, E);
    k_dinv<<<nBlk, TB>>>(indeg, dinv, N);
    k_scan1<<<nBlk, TB>>>(indeg, csr, part, N);
    k_scan2<<<1, 512>>>(part, nBlk);
    k_scan3<<<nBlk, TB>>>(csr, part, indeg, cursor, N);
    k_fill<<<(E + TB - 1) / TB, TB>>>(ei, dinv, csr, cursor, srcS, normS, E);

    const int grid = (N + 127) / 128;
    const int gGrid = ((size_t)N * 32 + TB - 1) / TB;
    // G1: h0 = leaky(x @ W_in + b_in) -> A
    k_gemm_mma<<<grid, TB>>>(x, W_in, b_in, bufA, N, ND, ND, 1);
    // conv1: t = h0 @ W_g -> B ; gather -> C
    k_gemm_mma<<<grid, TB>>>(bufA, W_g, nullptr, bufB, N, D, D, 0);
    k_gather<<<gGrid, TB>>>(bufB, csr, srcS, normS, dinv, b_g, bufC, N);
    // conv2: t = h1 @ W_g -> A ; gather -> B
    k_gemm_mma<<<grid, TB>>>(bufC, W_g, nullptr, bufA, N, D, D, 0);
    k_gather<<<gGrid, TB>>>(bufA, csr, srcS, normS, dinv, b_g, bufB, N);
    // G4: h3 = leaky(h2 @ W_o1 + b_o1) -> C
    k_gemm_mma<<<grid, TB>>>(bufB, W_o1, b_o1, bufC, N, D, D, 1);
    // out
    k_final<<<gGrid, TB>>>(bufC, W_o2, b_o2, out, N);
}

// round 11
// speedup vs baseline: 1.7626x; 1.1491x over previous
#include <cuda_runtime.h>
#include <cuda_bf16.h>
#include <cstdint>
#include <math.h>

#define NMAX 100000
#define EMAX 640000
#define D    128

// Scratch. bufA/C hold packed-split activations (uint32), bufB holds fp32 t.
__device__ uint32_t g_bufA[(size_t)NMAX * D];
__device__ float    g_bufB[(size_t)NMAX * D];
__device__ uint32_t g_bufC[(size_t)NMAX * D];
__device__ float    g_dinv[NMAX];
__device__ int      g_indeg[NMAX];
__device__ int      g_csr[NMAX + 1];
__device__ int      g_cursor[NMAX];
__device__ int      g_part[512];
__device__ int      g_srcS[EMAX];
__device__ float    g_normS[EMAX];
__device__ int      g_idx64;
// Pre-split weights (packed hi|lo<<16). W_in padded to 256 K-rows.
__device__ uint32_t g_WinPk[256 * D];
__device__ uint32_t g_WgPk[D * D];
__device__ uint32_t g_Wo1Pk[D * D];

__device__ __forceinline__ float leaky(float v) { return v >= 0.f ? v : 0.01f * v; }

__device__ __forceinline__ uint32_t packsplit(float v) {
    __nv_bfloat16 h = __float2bfloat16(v);
    __nv_bfloat16 l = __float2bfloat16(v - __bfloat162float(h));
    return (uint32_t)__bfloat16_as_ushort(h) | ((uint32_t)__bfloat16_as_ushort(l) << 16);
}
__device__ __forceinline__ uint32_t pack_hi(float a0, float a1) {
    __nv_bfloat16 h0 = __float2bfloat16(a0), h1 = __float2bfloat16(a1);
    return (uint32_t)__bfloat16_as_ushort(h0) | ((uint32_t)__bfloat16_as_ushort(h1) << 16);
}
__device__ __forceinline__ uint32_t pack_lo(float a0, float a1) {
    __nv_bfloat16 h0 = __float2bfloat16(a0), h1 = __float2bfloat16(a1);
    __nv_bfloat16 l0 = __float2bfloat16(a0 - __bfloat162float(h0));
    __nv_bfloat16 l1 = __float2bfloat16(a1 - __bfloat162float(h1));
    return (uint32_t)__bfloat16_as_ushort(l0) | ((uint32_t)__bfloat16_as_ushort(l1) << 16);
}

// ---------------------------------------------------------------------------
// m16n8k16 bf16 MMA + ldmatrix
// ---------------------------------------------------------------------------
__device__ __forceinline__ void mma16816(float* c, const uint32_t* a, const uint32_t* b) {
    asm volatile(
        "mma.sync.aligned.m16n8k16.row.col.f32.bf16.bf16.f32 "
        "{%0,%1,%2,%3}, {%4,%5,%6,%7}, {%8,%9}, {%0,%1,%2,%3};"
        : "+f"(c[0]), "+f"(c[1]), "+f"(c[2]), "+f"(c[3])
        : "r"(a[0]), "r"(a[1]), "r"(a[2]), "r"(a[3]), "r"(b[0]), "r"(b[1]));
}
__device__ __forceinline__ void ldsm4(uint32_t* r, uint32_t addr) {
    asm volatile("ldmatrix.sync.aligned.m8n8.x4.shared.b16 {%0,%1,%2,%3}, [%4];"
                 : "=r"(r[0]), "=r"(r[1]), "=r"(r[2]), "=r"(r[3]) : "r"(addr));
}

// ---------------------------------------------------------------------------
// GEMM: C = A[M,K] @ W[K,128].  128x128 tile, 8 warps, reg-prefetch, ldmatrix.
// A: fp32 (aPacked=0, G1) or packed-split uint32 (aPacked=1).  W: pre-split.
// mode 0: C0f = acc (fp32)
// mode 1: C0p = packsplit(leaky(acc + bias))
// mode 3: out[row*2+c] = sum_col leaky(acc+bias)*w2[col][c] + b2[c]  (fused)
// ---------------------------------------------------------------------------
#define RS 40  // smem row stride in halves

struct Frag { uint32_t aHi[8], aLo[8], bHi[8], bLo[8]; };

__device__ __forceinline__ void prefetch(
    Frag& f, const void* __restrict__ A, const uint32_t* __restrict__ Wpk,
    int rowBase, int M, int K, int lda, int k0, int tid, int aPacked)
{
    if (aPacked) {
#pragma unroll
        for (int i = 0; i < 8; i++) {
            int w = tid + i * 256;
            int row = w >> 4, kw = w & 15;
            int grow = rowBase + row, gk = k0 + kw * 2;
            uint2 p = make_uint2(0u, 0u);
            if (grow < M)
                p = *(const uint2*)((const uint32_t*)A + (size_t)grow * 128 + gk);
            f.aHi[i] = __byte_perm(p.x, p.y, 0x5410);
            f.aLo[i] = __byte_perm(p.x, p.y, 0x7632);
        }
    } else {
#pragma unroll
        for (int i = 0; i < 8; i++) {
            int w = tid + i * 256;
            int row = w >> 4, kw = w & 15;
            int grow = rowBase + row, gk = k0 + kw * 2;
            float a0 = 0.f, a1 = 0.f;
            if (grow < M) {
                const float* ap = (const float*)A + (size_t)grow * lda;
                if (gk < K)     a0 = ap[gk];
                if (gk + 1 < K) a1 = ap[gk + 1];
            }
            f.aHi[i] = pack_hi(a0, a1);
            f.aLo[i] = pack_lo(a0, a1);
        }
    }
#pragma unroll
    for (int i = 0; i < 8; i++) {
        int w = tid + i * 256;
        int n = w & 127, kw = w >> 7;
        int gk = k0 + kw * 2;
        uint32_t q0 = Wpk[(size_t)gk * D + n];
        uint32_t q1 = Wpk[(size_t)(gk + 1) * D + n];
        f.bHi[i] = __byte_perm(q0, q1, 0x5410);
        f.bLo[i] = __byte_perm(q0, q1, 0x7632);
    }
}

__global__ __launch_bounds__(256, 2) void k_gemm_mma(
    const void* __restrict__ A, const uint32_t* __restrict__ Wpk,
    const float* __restrict__ bias,
    float* __restrict__ C0f, uint32_t* __restrict__ C0p,
    const float* __restrict__ w2, const float* __restrict__ b2,
    float* __restrict__ outp,
    int M, int K, int lda, int aPacked, int mode)
{
    __shared__ float sBias[128];
    __shared__ float sW2[256];
    __shared__ float sProj[128][2];
    __shared__ __align__(16) __nv_bfloat16 AsHi[128 * RS];
    __shared__ __align__(16) __nv_bfloat16 AsLo[128 * RS];
    __shared__ __align__(16) __nv_bfloat16 BsHi[128 * RS];
    __shared__ __align__(16) __nv_bfloat16 BsLo[128 * RS];

    const int tid  = threadIdx.x;
    const int wid  = tid >> 5;
    const int lane = tid & 31;
    const int g    = lane >> 2;
    const int tig  = lane & 3;
    const int wm   = (wid >> 2) * 64;
    const int wn   = (wid & 3) * 32;
    const int rowBase = blockIdx.x * 128;

    if (mode != 0 && tid < 128) sBias[tid] = bias[tid];
    if (mode == 3) {
        sW2[tid] = w2[tid];        // 256 = 128x2
        if (tid < 128) { sProj[tid][0] = 0.f; sProj[tid][1] = 0.f; }
    }

    // ldmatrix address precompute
    const uint32_t aBaseH = (uint32_t)__cvta_generic_to_shared(AsHi);
    const uint32_t aBaseL = (uint32_t)__cvta_generic_to_shared(AsLo);
    const uint32_t bBaseH = (uint32_t)__cvta_generic_to_shared(BsHi);
    const uint32_t bBaseL = (uint32_t)__cvta_generic_to_shared(BsLo);
    const int aRow  = wm + (lane & 15);
    const int aColH = (lane >> 4) * 8;
    uint32_t aOff[4];
#pragma unroll
    for (int mt = 0; mt < 4; mt++)
        aOff[mt] = (uint32_t)(((aRow + mt * 16) * RS + aColH) * 2);
    const int bQ  = lane >> 3, bL7 = lane & 7;
    const int bNo = ((bQ >> 1) & 1) * 8 + bL7;
    const int bKo = (bQ & 1) * 8;
    uint32_t bOff[2];
#pragma unroll
    for (int p = 0; p < 2; p++)
        bOff[p] = (uint32_t)(((wn + p * 16 + bNo) * RS + bKo) * 2);

    float acc[4][4][4];
#pragma unroll
    for (int mt = 0; mt < 4; mt++)
#pragma unroll
        for (int nt = 0; nt < 4; nt++)
#pragma unroll
            for (int j = 0; j < 4; j++) acc[mt][nt][j] = 0.f;

    const int nStages = (K + 31) >> 5;
    Frag f;
    prefetch(f, A, Wpk, rowBase, M, K, lda, 0, tid, aPacked);

    for (int st = 0; st < nStages; st++) {
#pragma unroll
        for (int i = 0; i < 8; i++) {
            int w = tid + i * 256;
            int row = w >> 4, kw = w & 15;
            int so = row * RS + kw * 2;
            *(uint32_t*)(AsHi + so) = f.aHi[i];
            *(uint32_t*)(AsLo + so) = f.aLo[i];
            int n = w & 127, kb = (w >> 7) * 2;
            int sb = n * RS + kb;
            *(uint32_t*)(BsHi + sb) = f.bHi[i];
            *(uint32_t*)(BsLo + sb) = f.bLo[i];
        }
        __syncthreads();

        if (st + 1 < nStages)
            prefetch(f, A, Wpk, rowBase, M, K, lda, (st + 1) << 5, tid, aPacked);

#pragma unroll
        for (int kkB = 0; kkB < 64; kkB += 32) {
            uint32_t bh[2][4], bl[2][4];
            ldsm4(bh[0], bBaseH + bOff[0] + kkB);
            ldsm4(bh[1], bBaseH + bOff[1] + kkB);
            ldsm4(bl[0], bBaseL + bOff[0] + kkB);
            ldsm4(bl[1], bBaseL + bOff[1] + kkB);
#pragma unroll
            for (int mt = 0; mt < 4; mt++) {
                uint32_t ah[4], al[4];
                ldsm4(ah, aBaseH + aOff[mt] + kkB);
                ldsm4(al, aBaseL + aOff[mt] + kkB);
#pragma unroll
                for (int nt = 0; nt < 4; nt++) {
                    const uint32_t* bhp = &bh[nt >> 1][(nt & 1) * 2];
                    const uint32_t* blp = &bl[nt >> 1][(nt & 1) * 2];
                    mma16816(acc[mt][nt], ah, bhp);
                    mma16816(acc[mt][nt], ah, blp);
                    mma16816(acc[mt][nt], al, bhp);
                }
            }
        }
        __syncthreads();
    }

    // ---- epilogue ----
    if (mode == 3) {
#pragma unroll
        for (int mt = 0; mt < 4; mt++) {
            float p00 = 0.f, p01 = 0.f, p10 = 0.f, p11 = 0.f;
#pragma unroll
            for (int nt = 0; nt < 4; nt++) {
                int cn = wn + nt * 8 + 2 * tig;
                float b0 = sBias[cn], b1 = sBias[cn + 1];
                float w00 = sW2[cn * 2], w01 = sW2[cn * 2 + 1];
                float w10 = sW2[cn * 2 + 2], w11 = sW2[cn * 2 + 3];
                float* c = acc[mt][nt];
                float h0 = leaky(c[0] + b0), h1 = leaky(c[1] + b1);
                p00 += h0 * w00 + h1 * w10;
                p01 += h0 * w01 + h1 * w11;
                float h2 = leaky(c[2] + b0), h3 = leaky(c[3] + b1);
                p10 += h2 * w00 + h3 * w10;
                p11 += h2 * w01 + h3 * w11;
            }
            // quad reduce over tig
#pragma unroll
            for (int off = 1; off < 4; off <<= 1) {
                p00 += __shfl_xor_sync(0xFFFFFFFFu, p00, off);
                p01 += __shfl_xor_sync(0xFFFFFFFFu, p01, off);
                p10 += __shfl_xor_sync(0xFFFFFFFFu, p10, off);
                p11 += __shfl_xor_sync(0xFFFFFFFFu, p11, off);
            }
            if (tig == 0) {
                int lr = wm + mt * 16 + g;
                atomicAdd(&sProj[lr][0], p00);
                atomicAdd(&sProj[lr][1], p01);
                atomicAdd(&sProj[lr + 8][0], p10);
                atomicAdd(&sProj[lr + 8][1], p11);
            }
        }
        __syncthreads();
        if (tid < 256) {
            int lr = tid >> 1, c = tid & 1;
            int grow = rowBase + lr;
            if (grow < M) outp[(size_t)grow * 2 + c] = sProj[lr][c] + b2[c];
        }
        return;
    }

#pragma unroll
    for (int mt = 0; mt < 4; mt++) {
        int r0 = rowBase + wm + mt * 16 + g;
        int r1 = r0 + 8;
        bool v0 = r0 < M, v1 = r1 < M;
#pragma unroll
        for (int nt = 0; nt < 4; nt++) {
            int cn = wn + nt * 8 + 2 * tig;
            float* c = acc[mt][nt];
            if (mode == 1) {
                float b0 = sBias[cn], b1 = sBias[cn + 1];
                if (v0) {
                    uint2 o = { packsplit(leaky(c[0] + b0)), packsplit(leaky(c[1] + b1)) };
                    *(uint2*)(C0p + (size_t)r0 * D + cn) = o;
                }
                if (v1) {
                    uint2 o = { packsplit(leaky(c[2] + b0)), packsplit(leaky(c[3] + b1)) };
                    *(uint2*)(C0p + (size_t)r1 * D + cn) = o;
                }
            } else {
                if (v0) { float2 o = { c[0], c[1] }; *(float2*)(C0f + (size_t)r0 * D + cn) = o; }
                if (v1) { float2 o = { c[2], c[3] }; *(float2*)(C0f + (size_t)r1 * D + cn) = o; }
            }
        }
    }
}

// ---------------------------------------------------------------------------
// Weight pre-split: W_in (pad 256), W_g, W_o1 -> packed hi/lo
// ---------------------------------------------------------------------------
__global__ void k_splitW(const float* __restrict__ Win, const float* __restrict__ Wg,
                         const float* __restrict__ Wo1, int Kin)
{
    int i = blockIdx.x * blockDim.x + threadIdx.x;
    if (i >= 512 * D) return;
    int r = i >> 7, c = i & 127;
    if (r < 256) {
        float v = (r < Kin) ? Win[(size_t)r * D + c] : 0.f;
        g_WinPk[(size_t)r * D + c] = packsplit(v);
    } else if (r < 384) {
        g_WgPk[(size_t)(r - 256) * D + c] = packsplit(Wg[(size_t)(r - 256) * D + c]);
    } else {
        g_Wo1Pk[(size_t)(r - 384) * D + c] = packsplit(Wo1[(size_t)(r - 384) * D + c]);
    }
}

// ---------------------------------------------------------------------------
// Edge dtype detection + CSR build
// ---------------------------------------------------------------------------
__global__ void k_detect(const void* __restrict__ ei) {
    const long long* p = (const long long*)ei;
    int ok = 1;
    for (int i = 0; i < 16; i++) {
        long long v = p[i];
        if (v < 0 || v >= NMAX) ok = 0;
    }
    g_idx64 = ok;
}
__device__ __forceinline__ int edge_at(const void* ei, long long idx) {
    if (g_idx64) return (int)((const long long*)ei)[idx];
    return ((const int*)ei)[idx];
}

__global__ void k_zero(int* indeg, int n) {
    int i = blockIdx.x * blockDim.x + threadIdx.x;
    if (i < n) indeg[i] = 0;
}
__global__ void k_count(const void* __restrict__ ei, int* indeg, int e) {
    int i = blockIdx.x * blockDim.x + threadIdx.x;
    if (i < e) atomicAdd(&indeg[edge_at(ei, (long long)e + i)], 1);
}
__global__ void k_dinv(const int* __restrict__ indeg, float* dinv, int n) {
    int i = blockIdx.x * blockDim.x + threadIdx.x;
    if (i < n) dinv[i] = rsqrtf(1.0f + (float)indeg[i]);
}

__global__ void k_scan1(const int* __restrict__ indeg, int* __restrict__ csr,
                        int* __restrict__ part, int n)
{
    __shared__ int sh[256];
    int t = threadIdx.x;
    int i = blockIdx.x * 256 + t;
    int v = (i < n) ? indeg[i] : 0;
    sh[t] = v;
    __syncthreads();
#pragma unroll
    for (int off = 1; off < 256; off <<= 1) {
        int x = (t >= off) ? sh[t - off] : 0;
        __syncthreads();
        sh[t] += x;
        __syncthreads();
    }
    if (i < n) csr[i] = sh[t] - v;
    if (t == 255) part[blockIdx.x] = sh[t];
}

__global__ void k_scan2(int* __restrict__ part, int nb) {
    __shared__ int sh[512];
    int t = threadIdx.x;
    int v = (t < nb) ? part[t] : 0;
    sh[t] = v;
    __syncthreads();
#pragma unroll
    for (int off = 1; off < 512; off <<= 1) {
        int x = (t >= off) ? sh[t - off] : 0;
        __syncthreads();
        sh[t] += x;
        __syncthreads();
    }
    if (t < nb) part[t] = sh[t] - v;
}

__global__ void k_scan3(int* __restrict__ csr, const int* __restrict__ part,
                        const int* __restrict__ indeg, int* __restrict__ cursor, int n)
{
    int i = blockIdx.x * blockDim.x + threadIdx.x;
    if (i >= n) return;
    int base = csr[i] + part[i >> 8];
    csr[i] = base;
    cursor[i] = 0;
    if (i == n - 1) csr[n] = base + indeg[i];
}

__global__ void k_fill(const void* __restrict__ ei, const float* __restrict__ dinv,
                       const int* __restrict__ csr, int* __restrict__ cursor,
                       int* __restrict__ srcS, float* __restrict__ normS, int E)
{
    int i = blockIdx.x * blockDim.x + threadIdx.x;
    if (i >= E) return;
    int s = edge_at(ei, i);
    int d = edge_at(ei, (long long)E + i);
    int p = csr[d] + atomicAdd(&cursor[d], 1);
    srcS[p] = s;
    normS[p] = dinv[s] * dinv[d];
}

// ---------------------------------------------------------------------------
// Gather aggregation: one warp per dst node; fp32 in, packed-split out.
// ---------------------------------------------------------------------------
__global__ __launch_bounds__(256) void k_gather(
    const float* __restrict__ t, const int* __restrict__ csr,
    const int* __restrict__ srcS, const float* __restrict__ normS,
    const float* __restrict__ dinv, const float* __restrict__ bias,
    uint32_t* __restrict__ aggp, int N)
{
    int warp = (blockIdx.x * blockDim.x + threadIdx.x) >> 5;
    int lane = threadIdx.x & 31;
    if (warp >= N) return;
    int beg = csr[warp], end = csr[warp + 1];
    float dv = dinv[warp];
    float dv2 = dv * dv;
    float4 b4 = *(const float4*)(bias + lane * 4);
    float4 a  = *(const float4*)(t + (size_t)warp * D + lane * 4);
    float4 acc;
    acc.x = a.x * dv2 + b4.x;
    acc.y = a.y * dv2 + b4.y;
    acc.z = a.z * dv2 + b4.z;
    acc.w = a.w * dv2 + b4.w;
    for (int e = beg; e < end; e++) {
        int s = srcS[e];
        float nm = normS[e];
        float4 v = *(const float4*)(t + (size_t)s * D + lane * 4);
        acc.x += nm * v.x;
        acc.y += nm * v.y;
        acc.z += nm * v.z;
        acc.w += nm * v.w;
    }
    uint4 o;
    o.x = packsplit(acc.x);
    o.y = packsplit(acc.y);
    o.z = packsplit(acc.z);
    o.w = packsplit(acc.w);
    *(uint4*)(aggp + (size_t)warp * D + lane * 4) = o;
}

// ---------------------------------------------------------------------------
// Host launcher
// ---------------------------------------------------------------------------
extern "C" void kernel_launch(void* const* d_in, const int* in_sizes, int n_in,
                              void* d_out, int out_size)
{
    const float* x    = (const float*)d_in[0];
    const void*  ei   = d_in[1];
    const float* W_in = (const float*)d_in[3];
    const float* b_in = (const float*)d_in[4];
    const float* W_g  = (const float*)d_in[5];
    const float* b_g  = (const float*)d_in[6];
    const float* W_o1 = (const float*)d_in[7];
    const float* b_o1 = (const float*)d_in[8];
    const float* W_o2 = (const float*)d_in[9];
    const float* b_o2 = (const float*)d_in[10];
    float*       out  = (float*)d_out;

    const int ND = 239;
    const int N  = in_sizes[0] / ND;
    const int E  = in_sizes[1] / 2;

    uint32_t *bufA, *bufC, *WinPk, *WgPk, *Wo1Pk;
    float *bufB, *dinv, *normS;
    int *indeg, *csr, *cursor, *part, *srcS;
    cudaGetSymbolAddress((void**)&bufA,  g_bufA);
    cudaGetSymbolAddress((void**)&bufB,  g_bufB);
    cudaGetSymbolAddress((void**)&bufC,  g_bufC);
    cudaGetSymbolAddress((void**)&dinv,  g_dinv);
    cudaGetSymbolAddress((void**)&indeg, g_indeg);
    cudaGetSymbolAddress((void**)&csr,   g_csr);
    cudaGetSymbolAddress((void**)&cursor,g_cursor);
    cudaGetSymbolAddress((void**)&part,  g_part);
    cudaGetSymbolAddress((void**)&srcS,  g_srcS);
    cudaGetSymbolAddress((void**)&normS, g_normS);
    cudaGetSymbolAddress((void**)&WinPk, g_WinPk);
    cudaGetSymbolAddress((void**)&WgPk,  g_WgPk);
    cudaGetSymbolAddress((void**)&Wo1Pk, g_Wo1Pk);

    const int TB = 256;
    const int nBlk = (N + 255) / 256;

    k_detect<<<1, 1>>>(ei);
    k_zero<<<nBlk, TB>>>(indeg, N);
    k_count<<<(E + TB - 1) / TB, TB>>>(ei, indeg, E);
    k_dinv<<<nBlk, TB>>>(indeg, dinv, N);
    k_scan1<<<nBlk, TB>>>(indeg, csr, part, N);
    k_scan2<<<1, 512>>>(part, nBlk);
    k_scan3<<<nBlk, TB>>>(csr, part, indeg, cursor, N);
    k_fill<<<(E + TB - 1) / TB, TB>>>(ei, dinv, csr, cursor, srcS, normS, E);
    k_splitW<<<(512 * D + TB - 1) / TB, TB>>>(W_in, W_g, W_o1, ND);

    const int grid = (N + 127) / 128;
    const int gGrid = ((size_t)N * 32 + TB - 1) / TB;
    // G1: h0 = pk(leaky(x @ W_in + b_in)) -> A
    k_gemm_mma<<<grid, TB>>>(x, WinPk, b_in, nullptr, bufA, nullptr, nullptr, nullptr,
                             N, ND, ND, 0, 1);
    // G2: t1 = h0 @ W_g -> B (fp32)
    k_gemm_mma<<<grid, TB>>>(bufA, WgPk, nullptr, bufB, nullptr, nullptr, nullptr, nullptr,
                             N, D, D, 1, 0);
    k_gather<<<gGrid, TB>>>(bufB, csr, srcS, normS, dinv, b_g, bufC, N);
    // G3: t2 = h1 @ W_g -> B (fp32)
    k_gemm_mma<<<grid, TB>>>(bufC, WgPk, nullptr, bufB, nullptr, nullptr, nullptr, nullptr,
                             N, D, D, 1, 0);
    k_gather<<<gGrid, TB>>>(bufB, csr, srcS, normS, dinv, b_g, bufC, N);
    // G4: out = leaky(h2 @ W_o1 + b_o1) @ W_o2 + b_o2  (fully fused)
    k_gemm_mma<<<grid, TB>>>(bufC, Wo1Pk, b_o1, nullptr, nullptr, W_o2, b_o2, out,
                             N, D, D, 1, 3);
}